// round 3
// baseline (speedup 1.0000x reference)
#include <cuda_runtime.h>
#include <math.h>

// ---------------- problem constants ----------------
#define NROWS 25000
#define NQ    8000
#define XD    100
#define YD    120
#define HID   100
#define KPA   128   // padded K for fx mismatch (K=120)
#define KPB   112   // padded K for gy mismatch (K=100)

// ---------------- scratch (static device globals; no allocation) -------------
__device__ float g_h   [NROWS * HID];
__device__ float g_xmap[NROWS * YD];
__device__ float g_ymap[NROWS * XD];
__device__ float g_xrt [NROWS * XD];
__device__ float g_yrt [NROWS * YD];
__device__ float g_qAT [KPA * NQ];
__device__ float g_qBT [KPB * NQ];
__device__ float g_qnA [NQ];
__device__ float g_qnB [NQ];
__device__ float g_tnY [NROWS];
__device__ float g_tnX [NROWS];
__device__ unsigned long long g_keyA[NQ];
__device__ unsigned long long g_keyB[NQ];

// ---------------- init ----------------
__global__ void k_init(float* out) {
    int i = blockIdx.x * blockDim.x + threadIdx.x;
    if (i == 0) out[0] = 0.0f;
    if (i < NQ) { g_keyA[i] = ~0ULL; g_keyB[i] = ~0ULL; }
}

// ---------------- generic SGEMM with bias (+optional relu) -------------------
#define GBM 64
#define GBN 64
#define GBK 16
__global__ __launch_bounds__(256)
void k_gemm(const float* __restrict__ A, const float* __restrict__ B,
            const float* __restrict__ bias, float* __restrict__ C,
            int M, int N, int K, int relu)
{
    __shared__ float As[GBK][GBM + 1];
    __shared__ float Bs[GBK][GBN];
    int tid = threadIdx.x;
    int tx = tid & 15, ty = tid >> 4;
    int m0 = blockIdx.x * GBM, n0 = blockIdx.y * GBN;
    float acc[4][4] = {};

    for (int k0 = 0; k0 < K; k0 += GBK) {
#pragma unroll
        for (int i = 0; i < 4; i++) {
            int lin = tid + i * 256;
            int m = lin >> 4, k = lin & 15;
            int gm = m0 + m, gk = k0 + k;
            As[k][m] = (gm < M && gk < K) ? A[(size_t)gm * K + gk] : 0.0f;
        }
#pragma unroll
        for (int i = 0; i < 4; i++) {
            int lin = tid + i * 256;
            int k = lin >> 6, n = lin & 63;
            int gk = k0 + k, gn = n0 + n;
            Bs[k][n] = (gk < K && gn < N) ? B[(size_t)gk * N + gn] : 0.0f;
        }
        __syncthreads();
#pragma unroll
        for (int kk = 0; kk < GBK; kk++) {
            float a[4], b[4];
#pragma unroll
            for (int i = 0; i < 4; i++) a[i] = As[kk][ty * 4 + i];
#pragma unroll
            for (int j = 0; j < 4; j++) b[j] = Bs[kk][tx * 4 + j];
#pragma unroll
            for (int i = 0; i < 4; i++)
#pragma unroll
                for (int j = 0; j < 4; j++)
                    acc[i][j] = fmaf(a[i], b[j], acc[i][j]);
        }
        __syncthreads();
    }
#pragma unroll
    for (int i = 0; i < 4; i++) {
        int gm = m0 + ty * 4 + i;
        if (gm >= M) continue;
#pragma unroll
        for (int j = 0; j < 4; j++) {
            int gn = n0 + tx * 4 + j;
            if (gn >= N) continue;
            float v = acc[i][j] + bias[gn];
            if (relu) v = fmaxf(v, 0.0f);
            C[(size_t)gm * N + gn] = v;
        }
    }
}

// ---------------- mean of row norms of (A - B) -------------------------------
__global__ void k_rownorm_diff(const float* __restrict__ A, const float* __restrict__ B,
                               int M, int Kc, float scale, float* out)
{
    int w = threadIdx.x >> 5, lane = threadIdx.x & 31;
    int row = blockIdx.x * 8 + w;
    float r = 0.0f;
    if (row < M) {
        const float* a = A + (size_t)row * Kc;
        const float* b = B + (size_t)row * Kc;
        float s = 0.0f;
        for (int j = lane; j < Kc; j += 32) { float d = a[j] - b[j]; s = fmaf(d, d, s); }
#pragma unroll
        for (int o = 16; o; o >>= 1) s += __shfl_xor_sync(0xffffffffu, s, o);
        r = sqrtf(s);
    }
    __shared__ float sh[8];
    if (lane == 0) sh[w] = r;
    __syncthreads();
    if (threadIdx.x == 0) {
        float t = 0.0f;
#pragma unroll
        for (int i = 0; i < 8; i++) t += sh[i];
        atomicAdd(out, t * scale);
    }
}

__global__ void k_rownorm_sup(const float* __restrict__ A, const float* __restrict__ B,
                              const int* __restrict__ imap, int Kc, int aSel,
                              float scale, float* out)
{
    int w = threadIdx.x >> 5, lane = threadIdx.x & 31;
    int i = blockIdx.x * 8 + w;
    float r = 0.0f;
    if (i < NQ) {
        int ra = imap[2 * i + aSel];
        int rb = imap[2 * i + 1 - aSel];
        const float* a = A + (size_t)ra * Kc;
        const float* b = B + (size_t)rb * Kc;
        float s = 0.0f;
        for (int j = lane; j < Kc; j += 32) { float d = a[j] - b[j]; s = fmaf(d, d, s); }
#pragma unroll
        for (int o = 16; o; o >>= 1) s += __shfl_xor_sync(0xffffffffu, s, o);
        r = sqrtf(s);
    }
    __shared__ float sh[8];
    if (lane == 0) sh[w] = r;
    __syncthreads();
    if (threadIdx.x == 0) {
        float t = 0.0f;
#pragma unroll
        for (int i2 = 0; i2 < 8; i2++) t += sh[i2];
        atomicAdd(out, t * scale);
    }
}

// ---------------- squared row norms of target matrix -------------------------
__global__ void k_tnorm(const float* __restrict__ T, int M, int Kc, float* __restrict__ tn)
{
    int w = threadIdx.x >> 5, lane = threadIdx.x & 31;
    int row = blockIdx.x * 8 + w;
    if (row >= M) return;
    const float* a = T + (size_t)row * Kc;
    float s = 0.0f;
    for (int j = lane; j < Kc; j += 32) s = fmaf(a[j], a[j], s);
#pragma unroll
    for (int o = 16; o; o >>= 1) s += __shfl_xor_sync(0xffffffffu, s, o);
    if (lane == 0) tn[row] = s;
}

// ---------------- gather queries (transposed + padded) + query sq norms ------
__global__ void k_gather(const float* __restrict__ src, const int* __restrict__ imap,
                         int sel, int Kc, int KP, float* __restrict__ QT,
                         float* __restrict__ qn)
{
    int w = threadIdx.x >> 5, lane = threadIdx.x & 31;
    int i = blockIdx.x * 8 + w;
    if (i >= NQ) return;
    int r = imap[2 * i + sel];
    const float* a = src + (size_t)r * Kc;
    float s = 0.0f;
    for (int k = lane; k < KP; k += 32) {
        float v = (k < Kc) ? a[k] : 0.0f;
        QT[(size_t)k * NQ + i] = v;
        s = fmaf(v, v, s);
    }
#pragma unroll
    for (int o = 16; o; o >>= 1) s += __shfl_xor_sync(0xffffffffu, s, o);
    if (lane == 0) qn[i] = s;
}

// ---------------- 1-NN distance GEMM (packed fma.rn.f32x2 mainloop) ----------
// Block: 64 queries x 128-target tiles. 128 threads. Register tile: 8 queries
// (4 x f32x2 pairs along i) x 8 targets per thread.
#define MQ 64
#define MT 128
#define MK 16
__global__ __launch_bounds__(128, 4)
void k_mismatch(const float* __restrict__ QT,  // [KP][NQ]
                const float* __restrict__ qn,  // [NQ]
                const float* __restrict__ T,   // [NT][K] row-major
                const float* __restrict__ tn,  // [NT]
                unsigned long long* __restrict__ keys,
                int NT, int K, int KP)
{
    __shared__ float Qs[KPA][MQ];      // 32 KB
    __shared__ float Ts[MK][MT];       // 8 KB
    __shared__ float Tns[MT];
    __shared__ unsigned long long red[MQ];

    int tid = threadIdx.x;
    int tx = tid & 15;     // 16 target-groups of 8
    int ty = tid >> 4;     // 8 query-groups of 8
    int q0 = blockIdx.x * MQ;

    for (int lin = tid; lin < KP * MQ; lin += 128) {
        int k = lin >> 6, q = lin & 63;
        Qs[k][q] = QT[(size_t)k * NQ + q0 + q];
    }

    float qnr[8];
#pragma unroll
    for (int i = 0; i < 8; i++) qnr[i] = qn[q0 + ty * 8 + i];

    unsigned long long best[8];
#pragma unroll
    for (int i = 0; i < 8; i++) best[i] = ~0ULL;

    int chunk = (NT + gridDim.y - 1) / gridDim.y;
    int tStart = blockIdx.y * chunk;
    int tEnd = min(NT, tStart + chunk);

    __syncthreads();

    for (int t0 = tStart; t0 < tEnd; t0 += MT) {
        int tmine = t0 + tid;
        Tns[tid] = (tmine < tEnd) ? tn[tmine] : 0.0f;

        // acc2[ip][j]: f32x2 pair over queries (2ip, 2ip+1) for target j
        unsigned long long acc2[4][8];
#pragma unroll
        for (int ip = 0; ip < 4; ip++)
#pragma unroll
            for (int j = 0; j < 8; j++) acc2[ip][j] = 0ULL;

        for (int ks = 0; ks < KP; ks += MK) {
            {
                bool tok = (tmine < tEnd);
                const float* trow = T + (size_t)tmine * K + ks;
                if (tok && (ks + MK) <= K) {
#pragma unroll
                    for (int v4 = 0; v4 < 4; v4++) {
                        float4 v = *(const float4*)(trow + v4 * 4);
                        Ts[v4 * 4 + 0][tid] = v.x;
                        Ts[v4 * 4 + 1][tid] = v.y;
                        Ts[v4 * 4 + 2][tid] = v.z;
                        Ts[v4 * 4 + 3][tid] = v.w;
                    }
                } else {
#pragma unroll
                    for (int kk = 0; kk < MK; kk++)
                        Ts[kk][tid] = (tok && (ks + kk) < K) ? trow[kk] : 0.0f;
                }
            }
            __syncthreads();
#pragma unroll
            for (int kk = 0; kk < MK; kk++) {
                // 4 query-pairs as 64-bit loads (Qs row is 256B-aligned)
                const unsigned long long* qrow =
                    (const unsigned long long*)&Qs[ks + kk][ty * 8];
                unsigned long long a2[4];
                a2[0] = qrow[0]; a2[1] = qrow[1]; a2[2] = qrow[2]; a2[3] = qrow[3];
                // 8 target scalars, duplicated into both f32x2 halves
                float4 bv0 = *(const float4*)&Ts[kk][tx * 8];
                float4 bv1 = *(const float4*)&Ts[kk][tx * 8 + 4];
                float bf[8] = {bv0.x, bv0.y, bv0.z, bv0.w, bv1.x, bv1.y, bv1.z, bv1.w};
                unsigned long long bd[8];
#pragma unroll
                for (int j = 0; j < 8; j++)
                    asm("mov.b64 %0, {%1, %1};" : "=l"(bd[j]) : "f"(bf[j]));
#pragma unroll
                for (int ip = 0; ip < 4; ip++)
#pragma unroll
                    for (int j = 0; j < 8; j++)
                        asm("fma.rn.f32x2 %0, %1, %2, %0;"
                            : "+l"(acc2[ip][j]) : "l"(a2[ip]), "l"(bd[j]));
            }
            __syncthreads();
        }
        // epilogue: d2 = |q|^2 + |t|^2 - 2 q.t, clamp, fold into best key
#pragma unroll
        for (int j = 0; j < 8; j++) {
            int t = t0 + tx * 8 + j;
            if (t < tEnd) {
                float tnv = Tns[tx * 8 + j];
#pragma unroll
                for (int ip = 0; ip < 4; ip++) {
                    float lo, hi;
                    asm("mov.b64 {%0, %1}, %2;" : "=f"(lo), "=f"(hi) : "l"(acc2[ip][j]));
                    float d2lo = fmaxf(qnr[2 * ip] + tnv - 2.0f * lo, 0.0f);
                    float d2hi = fmaxf(qnr[2 * ip + 1] + tnv - 2.0f * hi, 0.0f);
                    unsigned long long klo =
                        ((unsigned long long)__float_as_uint(d2lo) << 32) | (unsigned int)t;
                    unsigned long long khi =
                        ((unsigned long long)__float_as_uint(d2hi) << 32) | (unsigned int)t;
                    if (klo < best[2 * ip]) best[2 * ip] = klo;
                    if (khi < best[2 * ip + 1]) best[2 * ip + 1] = khi;
                }
            }
        }
        __syncthreads();  // protect Tns before next tile's overwrite
    }

    if (tid < MQ) red[tid] = ~0ULL;
    __syncthreads();
#pragma unroll
    for (int i = 0; i < 8; i++) atomicMin(&red[ty * 8 + i], best[i]);
    __syncthreads();
    if (tid < MQ) atomicMin(&keys[q0 + tid], red[tid]);
}

// ---------------- finalize mismatch terms ----------------
__global__ void k_finish(const unsigned long long* __restrict__ keys,
                         const int* __restrict__ imap, int sel, float scale, float* out)
{
    __shared__ float sh[256];
    int i = blockIdx.x * blockDim.x + threadIdx.x;
    float c = 0.0f;
    if (i < NQ) {
        unsigned long long k = keys[i];
        float d2 = __uint_as_float((unsigned int)(k >> 32));
        int nn = (int)(unsigned int)(k & 0xffffffffu);
        float v = sqrtf(d2);
        if (nn != imap[2 * i + sel]) c = ceilf(v) - floorf(v);
    }
    sh[threadIdx.x] = c;
    __syncthreads();
    for (int s = 128; s; s >>= 1) {
        if (threadIdx.x < s) sh[threadIdx.x] += sh[threadIdx.x + s];
        __syncthreads();
    }
    if (threadIdx.x == 0) atomicAdd(out, sh[0] * scale);
}

// ---------------- host orchestration ----------------
extern "C" void kernel_launch(void* const* d_in, const int* in_sizes, int n_in,
                              void* d_out, int out_size)
{
    const float* x_w   = (const float*)d_in[0];
    const float* y_w   = (const float*)d_in[1];
    const float* fx_w1 = (const float*)d_in[2];
    const float* fx_b1 = (const float*)d_in[3];
    const float* fx_w2 = (const float*)d_in[4];
    const float* fx_b2 = (const float*)d_in[5];
    const float* gy_w1 = (const float*)d_in[6];
    const float* gy_b1 = (const float*)d_in[7];
    const float* gy_w2 = (const float*)d_in[8];
    const float* gy_b2 = (const float*)d_in[9];
    const int*   imap  = (const int*)d_in[10];
    float* out = (float*)d_out;

    float *h, *xmap, *ymap, *xrt, *yrt, *qAT, *qBT, *qnA, *qnB, *tnY, *tnX;
    unsigned long long *keyA, *keyB;
    cudaGetSymbolAddress((void**)&h,    g_h);
    cudaGetSymbolAddress((void**)&xmap, g_xmap);
    cudaGetSymbolAddress((void**)&ymap, g_ymap);
    cudaGetSymbolAddress((void**)&xrt,  g_xrt);
    cudaGetSymbolAddress((void**)&yrt,  g_yrt);
    cudaGetSymbolAddress((void**)&qAT,  g_qAT);
    cudaGetSymbolAddress((void**)&qBT,  g_qBT);
    cudaGetSymbolAddress((void**)&qnA,  g_qnA);
    cudaGetSymbolAddress((void**)&qnB,  g_qnB);
    cudaGetSymbolAddress((void**)&tnY,  g_tnY);
    cudaGetSymbolAddress((void**)&tnX,  g_tnX);
    cudaGetSymbolAddress((void**)&keyA, g_keyA);
    cudaGetSymbolAddress((void**)&keyB, g_keyB);

    k_init<<<(NQ + 255) / 256, 256>>>(out);

    dim3 gg((NROWS + GBM - 1) / GBM, 2);
    k_gemm<<<gg, 256>>>(x_w, fx_w1, fx_b1, h,    NROWS, HID, XD,  1);
    k_gemm<<<gg, 256>>>(h,   fx_w2, fx_b2, xmap, NROWS, YD,  HID, 0);
    k_gemm<<<gg, 256>>>(y_w, gy_w1, gy_b1, h,    NROWS, HID, YD,  1);
    k_gemm<<<gg, 256>>>(h,   gy_w2, gy_b2, ymap, NROWS, XD,  HID, 0);
    k_gemm<<<gg, 256>>>(xmap, gy_w1, gy_b1, h,   NROWS, HID, YD,  1);
    k_gemm<<<gg, 256>>>(h,    gy_w2, gy_b2, xrt, NROWS, XD,  HID, 0);
    k_gemm<<<gg, 256>>>(ymap, fx_w1, fx_b1, h,   NROWS, HID, XD,  1);
    k_gemm<<<gg, 256>>>(h,    fx_w2, fx_b2, yrt, NROWS, YD,  HID, 0);

    k_rownorm_diff<<<(NROWS + 7) / 8, 256>>>(xrt, x_w, NROWS, XD, 1.0f / NROWS, out);
    k_rownorm_diff<<<(NROWS + 7) / 8, 256>>>(yrt, y_w, NROWS, YD, 1.0f / NROWS, out);
    k_rownorm_sup<<<(NQ + 7) / 8, 256>>>(xmap, y_w, imap, YD, 0, 1.0f / NQ, out);
    k_rownorm_sup<<<(NQ + 7) / 8, 256>>>(ymap, x_w, imap, XD, 1, 1.0f / NQ, out);

    k_tnorm<<<(NROWS + 7) / 8, 256>>>(y_w, NROWS, YD, tnY);
    k_tnorm<<<(NROWS + 7) / 8, 256>>>(x_w, NROWS, XD, tnX);
    k_gather<<<(NQ + 7) / 8, 256>>>(xmap, imap, 0, YD, KPA, qAT, qnA);
    k_gather<<<(NQ + 7) / 8, 256>>>(ymap, imap, 1, XD, KPB, qBT, qnB);

    // 19 y-chunks -> 2375 blocks ~= 4 full waves at occupancy 4 on 148 SMs
    dim3 mg(NQ / MQ, 19);
    k_mismatch<<<mg, 128>>>(qAT, qnA, y_w, tnY, keyA, NROWS, YD, KPA);
    k_mismatch<<<mg, 128>>>(qBT, qnB, x_w, tnX, keyB, NROWS, XD, KPB);

    k_finish<<<(NQ + 255) / 256, 256>>>(keyA, imap, 0, 1.0f / NQ, out);
    k_finish<<<(NQ + 255) / 256, 256>>>(keyB, imap, 1, 1.0f / NQ, out);
}

// round 5
// speedup vs baseline: 5.0652x; 5.0652x over previous
#include <cuda_runtime.h>
#include <cuda_bf16.h>
#include <math.h>
#include <stdint.h>

// ---------------- problem constants ----------------
#define NROWS 25000
#define NQ    8000
#define XD    100
#define YD    120
#define HID   100
#define KP    128
#define NQPAD 8064          // 63*128
#define NTPAD 25088         // 196*128
#define QTILES 63
#define GSPLIT 14
#define NCH_PER 14          // 196 chunks / 14
#define CSHIFT 8.0f

// ---------------- scratch ----------------
__device__ float g_h   [NROWS * HID];
__device__ float g_xmap[NROWS * YD];
__device__ float g_ymap[NROWS * XD];
__device__ float g_xrt [NROWS * XD];
__device__ float g_yrt [NROWS * YD];
__device__ float g_tnY [NROWS];
__device__ float g_tnX [NROWS];
__device__ __align__(16) __nv_bfloat16 g_Qb[NQPAD * KP];
__device__ __align__(16) __nv_bfloat16 g_Tb[NTPAD * KP];
__device__ unsigned int g_mb [NQ];
__device__ float        g_pref[NQ];

// ---------------- helpers ----------------
__device__ __forceinline__ uint32_t smem_u32(const void* p) {
    uint32_t a;
    asm("{ .reg .u64 t; cvta.to.shared.u64 t, %1; cvt.u32.u64 %0, t; }" : "=r"(a) : "l"(p));
    return a;
}
__device__ __forceinline__ void cpa16(uint32_t dst, const void* src) {
    asm volatile("cp.async.cg.shared.global [%0], [%1], 16;" :: "r"(dst), "l"(src));
}
#define CP_COMMIT() asm volatile("cp.async.commit_group;" ::: "memory")
#define CP_WAIT0()  asm volatile("cp.async.wait_group 0;" ::: "memory")

// ---------------- small kernels ----------------
__global__ void k_init(float* out) {
    if (blockIdx.x == 0 && threadIdx.x == 0) out[0] = 0.0f;
}
__global__ void k_reset() {
    int i = blockIdx.x * 256 + threadIdx.x;
    if (i < NQ) g_mb[i] = 0x7F800000u;
}

// ---------------- SGEMM with bias (+relu) for MLPs ----------------
#define GBM 64
#define GBN 64
#define GBK 16
__global__ __launch_bounds__(256)
void k_gemm(const float* __restrict__ A, const float* __restrict__ B,
            const float* __restrict__ bias, float* __restrict__ C,
            int M, int N, int K, int relu)
{
    __shared__ float As[GBK][GBM + 1];
    __shared__ float Bs[GBK][GBN];
    int tid = threadIdx.x, tx = tid & 15, ty = tid >> 4;
    int m0 = blockIdx.x * GBM, n0 = blockIdx.y * GBN;
    float acc[4][4] = {};
    for (int k0 = 0; k0 < K; k0 += GBK) {
#pragma unroll
        for (int i = 0; i < 4; i++) {
            int lin = tid + i * 256, m = lin >> 4, k = lin & 15;
            int gm = m0 + m, gk = k0 + k;
            As[k][m] = (gm < M && gk < K) ? A[(size_t)gm * K + gk] : 0.0f;
        }
#pragma unroll
        for (int i = 0; i < 4; i++) {
            int lin = tid + i * 256, k = lin >> 6, n = lin & 63;
            int gk = k0 + k, gn = n0 + n;
            Bs[k][n] = (gk < K && gn < N) ? B[(size_t)gk * N + gn] : 0.0f;
        }
        __syncthreads();
#pragma unroll
        for (int kk = 0; kk < GBK; kk++) {
            float a[4], b[4];
#pragma unroll
            for (int i = 0; i < 4; i++) a[i] = As[kk][ty * 4 + i];
#pragma unroll
            for (int j = 0; j < 4; j++) b[j] = Bs[kk][tx * 4 + j];
#pragma unroll
            for (int i = 0; i < 4; i++)
#pragma unroll
                for (int j = 0; j < 4; j++) acc[i][j] = fmaf(a[i], b[j], acc[i][j]);
        }
        __syncthreads();
    }
#pragma unroll
    for (int i = 0; i < 4; i++) {
        int gm = m0 + ty * 4 + i;
        if (gm >= M) continue;
#pragma unroll
        for (int j = 0; j < 4; j++) {
            int gn = n0 + tx * 4 + j;
            if (gn >= N) continue;
            float v = acc[i][j] + bias[gn];
            if (relu) v = fmaxf(v, 0.0f);
            C[(size_t)gm * N + gn] = v;
        }
    }
}

// ---------------- reductions ----------------
__global__ void k_rownorm_diff(const float* __restrict__ A, const float* __restrict__ B,
                               int M, int Kc, float scale, float* out)
{
    int w = threadIdx.x >> 5, lane = threadIdx.x & 31;
    int row = blockIdx.x * 8 + w;
    float r = 0.0f;
    if (row < M) {
        const float* a = A + (size_t)row * Kc;
        const float* b = B + (size_t)row * Kc;
        float s = 0.0f;
        for (int j = lane; j < Kc; j += 32) { float d = a[j] - b[j]; s = fmaf(d, d, s); }
#pragma unroll
        for (int o = 16; o; o >>= 1) s += __shfl_xor_sync(0xffffffffu, s, o);
        r = sqrtf(s);
    }
    __shared__ float sh[8];
    if (lane == 0) sh[w] = r;
    __syncthreads();
    if (threadIdx.x == 0) {
        float t = 0.0f;
#pragma unroll
        for (int i = 0; i < 8; i++) t += sh[i];
        atomicAdd(out, t * scale);
    }
}

__global__ void k_rownorm_sup(const float* __restrict__ A, const float* __restrict__ B,
                              const int* __restrict__ imap, int Kc, int aSel,
                              float scale, float* out)
{
    int w = threadIdx.x >> 5, lane = threadIdx.x & 31;
    int i = blockIdx.x * 8 + w;
    float r = 0.0f;
    if (i < NQ) {
        const float* a = A + (size_t)imap[2 * i + aSel] * Kc;
        const float* b = B + (size_t)imap[2 * i + 1 - aSel] * Kc;
        float s = 0.0f;
        for (int j = lane; j < Kc; j += 32) { float d = a[j] - b[j]; s = fmaf(d, d, s); }
#pragma unroll
        for (int o = 16; o; o >>= 1) s += __shfl_xor_sync(0xffffffffu, s, o);
        r = sqrtf(s);
    }
    __shared__ float sh[8];
    if (lane == 0) sh[w] = r;
    __syncthreads();
    if (threadIdx.x == 0) {
        float t = 0.0f;
#pragma unroll
        for (int k = 0; k < 8; k++) t += sh[k];
        atomicAdd(out, t * scale);
    }
}

__global__ void k_tnorm(const float* __restrict__ T, int M, int Kc, float* __restrict__ tn)
{
    int w = threadIdx.x >> 5, lane = threadIdx.x & 31;
    int row = blockIdx.x * 8 + w;
    if (row >= M) return;
    const float* a = T + (size_t)row * Kc;
    float s = 0.0f;
    for (int j = lane; j < Kc; j += 32) s = fmaf(a[j], a[j], s);
#pragma unroll
    for (int o = 16; o; o >>= 1) s += __shfl_xor_sync(0xffffffffu, s, o);
    if (lane == 0) tn[row] = s;
}

// ---------------- bf16 prep ----------------
// T': [NTPAD][128]: cols<K = t; col K = bf16(8+tn); col K+1 = residual; pad rows big.
__global__ void k_prep_t(const float* __restrict__ T, const float* __restrict__ tn, int K)
{
    int idx = blockIdx.x * 256 + threadIdx.x;
    if (idx >= NTPAD * KP) return;
    int row = idx >> 7, col = idx & 127;
    float v = 0.0f;
    if (row < NROWS) {
        if (col < K) v = T[(size_t)row * K + col];
        else if (col == K) v = CSHIFT + tn[row];
        else if (col == K + 1) {
            float s = CSHIFT + tn[row];
            v = s - __bfloat162float(__float2bfloat16(s));
        }
    } else if (col == K) v = 1.0e6f;
    g_Tb[idx] = __float2bfloat16(v);
}
// Q': [NQPAD][128]: cols<K = -2*mapped[imap]; cols K,K+1 = 1.
__global__ void k_prep_q(const float* __restrict__ mapped, const int* __restrict__ imap,
                         int sel, int K)
{
    int idx = blockIdx.x * 256 + threadIdx.x;
    if (idx >= NQPAD * KP) return;
    int row = idx >> 7, col = idx & 127;
    float v = 0.0f;
    if (row < NQ) {
        if (col < K) v = -2.0f * mapped[(size_t)imap[2 * row + sel] * K + col];
        else if (col <= K + 1) v = 1.0f;
    }
    g_Qb[idx] = __float2bfloat16(v);
}

// p_ref[q] = bf16-dot proxy at t = imap[2q+sel] (same quantized inputs as GEMM)
__global__ void k_pref(const int* __restrict__ imap, int sel)
{
    int w = threadIdx.x >> 5, lane = threadIdx.x & 31;
    int q = blockIdx.x * 8 + w;
    if (q >= NQ) return;
    int t = imap[2 * q + sel];
    const __nv_bfloat16* qr = g_Qb + (size_t)q * KP;
    const __nv_bfloat16* tr = g_Tb + (size_t)t * KP;
    float s = 0.0f;
#pragma unroll
    for (int k = lane; k < KP; k += 32)
        s = fmaf(__bfloat162float(qr[k]), __bfloat162float(tr[k]), s);
#pragma unroll
    for (int o = 16; o; o >>= 1) s += __shfl_xor_sync(0xffffffffu, s, o);
    if (lane == 0) g_pref[q] = s;
}

// ---------------- mma.sync 1-NN proxy-min ----------------
// CTA: 128 queries x 128-target chunks, K=128 bf16. 8 warps (2x4), warp tile 64x32.
#define PITCH_B 272                      // bytes per smem row (136 bf16)
#define SM_B0   (128 * PITCH_B)          // 34816: A tile at 0
#define SM_B1   (SM_B0 + 128 * PITCH_B)
#define SM_MIN  (SM_B1 + 128 * PITCH_B)  // 104448
#define SMEM_NN (SM_MIN + 512)

__global__ __launch_bounds__(256, 2)
void k_nn(const char* __restrict__ Qb, const char* __restrict__ Tb)
{
    extern __shared__ __align__(16) char dsm[];
    uint32_t sbase = smem_u32(dsm);
    unsigned* smin = (unsigned*)(dsm + SM_MIN);
    int tid = threadIdx.x, lane = tid & 31, wid = tid >> 5;
    int warp_m = wid >> 2, warp_n = wid & 3;
    int qtile = blockIdx.x, g = blockIdx.y;

    // A tile (queries) + B chunk 0 via cp.async
    {
        const char* Ag = Qb + (size_t)qtile * 32768;
        const char* Bg = Tb + (size_t)(g * NCH_PER) * 32768;
        for (int i = tid; i < 2048; i += 256) {
            int row = i >> 4, c16 = (i & 15) * 16;
            cpa16(sbase + row * PITCH_B + c16, Ag + row * 256 + c16);
            cpa16(sbase + SM_B0 + row * PITCH_B + c16, Bg + row * 256 + c16);
        }
        CP_COMMIT();
    }
    if (tid < 128) smin[tid] = 0x7F800000u;

    float best0[4], best1[4];
#pragma unroll
    for (int mf = 0; mf < 4; mf++) { best0[mf] = 1e30f; best1[mf] = 1e30f; }

    // ldmatrix base addresses
    uint32_t aAddr = sbase + (uint32_t)((warp_m * 64 + (lane & 15)) * PITCH_B
                                        + ((lane >> 4) & 1) * 16);
    uint32_t bOff  = (uint32_t)((warp_n * 32 + (lane & 7)) * PITCH_B
                                + ((lane >> 3) & 1) * 16);

    for (int c = 0; c < NCH_PER; c++) {
        CP_WAIT0();
        __syncthreads();
        if (c + 1 < NCH_PER) {
            const char* Bg = Tb + (size_t)(g * NCH_PER + c + 1) * 32768;
            uint32_t dstb = sbase + (((c + 1) & 1) ? SM_B1 : SM_B0);
            for (int i = tid; i < 2048; i += 256) {
                int row = i >> 4, c16 = (i & 15) * 16;
                cpa16(dstb + row * PITCH_B + c16, Bg + row * 256 + c16);
            }
            CP_COMMIT();
        }
        uint32_t bAddr = sbase + ((c & 1) ? SM_B1 : SM_B0) + bOff;

        float acc[4][4][4];
#pragma unroll
        for (int mf = 0; mf < 4; mf++)
#pragma unroll
            for (int nf = 0; nf < 4; nf++)
#pragma unroll
                for (int r = 0; r < 4; r++) acc[mf][nf][r] = 0.0f;

#pragma unroll
        for (int ks = 0; ks < 8; ks++) {
            uint32_t a[4][4], b[4][2];
#pragma unroll
            for (int mf = 0; mf < 4; mf++)
                asm volatile(
                    "ldmatrix.sync.aligned.m8n8.x4.shared.b16 {%0,%1,%2,%3}, [%4];"
                    : "=r"(a[mf][0]), "=r"(a[mf][1]), "=r"(a[mf][2]), "=r"(a[mf][3])
                    : "r"(aAddr + mf * 16 * PITCH_B + ks * 32));
#pragma unroll
            for (int nf = 0; nf < 4; nf++)
                asm volatile(
                    "ldmatrix.sync.aligned.m8n8.x2.shared.b16 {%0,%1}, [%2];"
                    : "=r"(b[nf][0]), "=r"(b[nf][1])
                    : "r"(bAddr + nf * 8 * PITCH_B + ks * 32));
#pragma unroll
            for (int mf = 0; mf < 4; mf++)
#pragma unroll
                for (int nf = 0; nf < 4; nf++)
                    asm volatile(
                        "mma.sync.aligned.m16n8k16.row.col.f32.bf16.bf16.f32 "
                        "{%0,%1,%2,%3}, {%4,%5,%6,%7}, {%8,%9}, {%0,%1,%2,%3};"
                        : "+f"(acc[mf][nf][0]), "+f"(acc[mf][nf][1]),
                          "+f"(acc[mf][nf][2]), "+f"(acc[mf][nf][3])
                        : "r"(a[mf][0]), "r"(a[mf][1]), "r"(a[mf][2]), "r"(a[mf][3]),
                          "r"(b[nf][0]), "r"(b[nf][1]));
        }
        // fold chunk mins into running per-row bests
#pragma unroll
        for (int mf = 0; mf < 4; mf++)
#pragma unroll
            for (int nf = 0; nf < 4; nf++) {
                best0[mf] = fminf(best0[mf], fminf(acc[mf][nf][0], acc[mf][nf][1]));
                best1[mf] = fminf(best1[mf], fminf(acc[mf][nf][2], acc[mf][nf][3]));
            }
    }

    // reduce: lanes sharing a row (lane%4 group), then shared, then global
#pragma unroll
    for (int mf = 0; mf < 4; mf++) {
        float v0 = best0[mf], v1 = best1[mf];
        v0 = fminf(v0, __shfl_xor_sync(0xffffffffu, v0, 1));
        v0 = fminf(v0, __shfl_xor_sync(0xffffffffu, v0, 2));
        v1 = fminf(v1, __shfl_xor_sync(0xffffffffu, v1, 1));
        v1 = fminf(v1, __shfl_xor_sync(0xffffffffu, v1, 2));
        if ((lane & 3) == 0) {
            int r = warp_m * 64 + mf * 16 + (lane >> 2);
            atomicMin(&smin[r], __float_as_uint(v0));
            atomicMin(&smin[r + 8], __float_as_uint(v1));
        }
    }
    __syncthreads();
    if (tid < 128) {
        int q = qtile * 128 + tid;
        if (q < NQ) atomicMin(&g_mb[q], smin[tid]);
    }
}

// ---------------- finalize mismatch ----------------
__global__ void k_finish_nn(float scale, float* out)
{
    __shared__ float sh[256];
    int i = blockIdx.x * 256 + threadIdx.x;
    float c = 0.0f;
    if (i < NQ) {
        float m = __uint_as_float(g_mb[i]);
        if (m < g_pref[i] - 1e-4f) c = 1.0f;
    }
    sh[threadIdx.x] = c;
    __syncthreads();
    for (int s = 128; s; s >>= 1) {
        if (threadIdx.x < s) sh[threadIdx.x] += sh[threadIdx.x + s];
        __syncthreads();
    }
    if (threadIdx.x == 0) atomicAdd(out, sh[0] * scale);
}

// ---------------- host ----------------
extern "C" void kernel_launch(void* const* d_in, const int* in_sizes, int n_in,
                              void* d_out, int out_size)
{
    const float* x_w   = (const float*)d_in[0];
    const float* y_w   = (const float*)d_in[1];
    const float* fx_w1 = (const float*)d_in[2];
    const float* fx_b1 = (const float*)d_in[3];
    const float* fx_w2 = (const float*)d_in[4];
    const float* fx_b2 = (const float*)d_in[5];
    const float* gy_w1 = (const float*)d_in[6];
    const float* gy_b1 = (const float*)d_in[7];
    const float* gy_w2 = (const float*)d_in[8];
    const float* gy_b2 = (const float*)d_in[9];
    const int*   imap  = (const int*)d_in[10];
    float* out = (float*)d_out;

    float *h, *xmap, *ymap, *xrt, *yrt, *tnY, *tnX;
    char *Qb, *Tb;
    cudaGetSymbolAddress((void**)&h,    g_h);
    cudaGetSymbolAddress((void**)&xmap, g_xmap);
    cudaGetSymbolAddress((void**)&ymap, g_ymap);
    cudaGetSymbolAddress((void**)&xrt,  g_xrt);
    cudaGetSymbolAddress((void**)&yrt,  g_yrt);
    cudaGetSymbolAddress((void**)&tnY,  g_tnY);
    cudaGetSymbolAddress((void**)&tnX,  g_tnX);
    cudaGetSymbolAddress((void**)&Qb,   g_Qb);
    cudaGetSymbolAddress((void**)&Tb,   g_Tb);

    cudaFuncSetAttribute(k_nn, cudaFuncAttributeMaxDynamicSharedMemorySize, SMEM_NN);

    k_init<<<1, 32>>>(out);

    dim3 gg((NROWS + GBM - 1) / GBM, 2);
    k_gemm<<<gg, 256>>>(x_w, fx_w1, fx_b1, h,    NROWS, HID, XD,  1);
    k_gemm<<<gg, 256>>>(h,   fx_w2, fx_b2, xmap, NROWS, YD,  HID, 0);
    k_gemm<<<gg, 256>>>(y_w, gy_w1, gy_b1, h,    NROWS, HID, YD,  1);
    k_gemm<<<gg, 256>>>(h,   gy_w2, gy_b2, ymap, NROWS, XD,  HID, 0);
    k_gemm<<<gg, 256>>>(xmap, gy_w1, gy_b1, h,   NROWS, HID, YD,  1);
    k_gemm<<<gg, 256>>>(h,    gy_w2, gy_b2, xrt, NROWS, XD,  HID, 0);
    k_gemm<<<gg, 256>>>(ymap, fx_w1, fx_b1, h,   NROWS, HID, XD,  1);
    k_gemm<<<gg, 256>>>(h,    fx_w2, fx_b2, yrt, NROWS, YD,  HID, 0);

    k_rownorm_diff<<<(NROWS + 7) / 8, 256>>>(xrt, x_w, NROWS, XD, 1.0f / NROWS, out);
    k_rownorm_diff<<<(NROWS + 7) / 8, 256>>>(yrt, y_w, NROWS, YD, 1.0f / NROWS, out);
    k_rownorm_sup<<<(NQ + 7) / 8, 256>>>(xmap, y_w, imap, YD, 0, 1.0f / NQ, out);
    k_rownorm_sup<<<(NQ + 7) / 8, 256>>>(ymap, x_w, imap, XD, 1, 1.0f / NQ, out);

    k_tnorm<<<(NROWS + 7) / 8, 256>>>(y_w, NROWS, YD, tnY);
    k_tnorm<<<(NROWS + 7) / 8, 256>>>(x_w, NROWS, XD, tnX);

    dim3 ng(QTILES, GSPLIT);
    // side A: queries = x_mapped[imap0], targets = y_weight
    k_prep_t<<<(NTPAD * KP + 255) / 256, 256>>>(y_w, tnY, YD);
    k_prep_q<<<(NQPAD * KP + 255) / 256, 256>>>(xmap, imap, 0, YD);
    k_reset<<<(NQ + 255) / 256, 256>>>();
    k_pref<<<(NQ + 7) / 8, 256>>>(imap, 0);
    k_nn<<<ng, 256, SMEM_NN>>>(Qb, Tb);
    k_finish_nn<<<(NQ + 255) / 256, 256>>>(1.0f / NQ, out);
    // side B: queries = y_mapped[imap1], targets = x_weight
    k_prep_t<<<(NTPAD * KP + 255) / 256, 256>>>(x_w, tnX, XD);
    k_prep_q<<<(NQPAD * KP + 255) / 256, 256>>>(ymap, imap, 1, XD);
    k_reset<<<(NQ + 255) / 256, 256>>>();
    k_pref<<<(NQ + 7) / 8, 256>>>(imap, 1);
    k_nn<<<ng, 256, SMEM_NN>>>(Qb, Tb);
    k_finish_nn<<<(NQ + 255) / 256, 256>>>(1.0f / NQ, out);
}

// round 6
// speedup vs baseline: 5.7982x; 1.1447x over previous
#include <cuda_runtime.h>
#include <cuda_bf16.h>
#include <math.h>
#include <stdint.h>

// ---------------- problem constants ----------------
#define NROWS 25000
#define NQ    8000
#define XD    100
#define YD    120
#define HID   100
#define KP    128
#define NQPAD 8064          // 63*128
#define NTPAD 25088         // 196*128
#define QTILES 63
#define GSPLIT 14
#define NCH_PER 14          // 196 chunks / 14
#define CSHIFT 8.0f

// ---------------- scratch ----------------
__device__ float g_xmap[NROWS * YD];
__device__ float g_ymap[NROWS * XD];
__device__ float g_xrt [NROWS * XD];
__device__ float g_yrt [NROWS * YD];
__device__ float g_tnY [NROWS];
__device__ float g_tnX [NROWS];
__device__ __align__(16) __nv_bfloat16 g_Qb[NQPAD * KP];
__device__ __align__(16) __nv_bfloat16 g_Tb[NTPAD * KP];
__device__ unsigned int g_mb [NQ];
__device__ float        g_pref[NQ];

// ---------------- helpers ----------------
__device__ __forceinline__ uint32_t smem_u32(const void* p) {
    uint32_t a;
    asm("{ .reg .u64 t; cvta.to.shared.u64 t, %1; cvt.u32.u64 %0, t; }" : "=r"(a) : "l"(p));
    return a;
}
__device__ __forceinline__ void cpa16(uint32_t dst, const void* src) {
    asm volatile("cp.async.cg.shared.global [%0], [%1], 16;" :: "r"(dst), "l"(src));
}
#define CP_COMMIT() asm volatile("cp.async.commit_group;" ::: "memory")
#define CP_WAIT0()  asm volatile("cp.async.wait_group 0;" ::: "memory")

__device__ __forceinline__ uint32_t f2tf32(float v) {
    uint32_t r;
    asm("cvt.rna.tf32.f32 %0, %1;" : "=r"(r) : "f"(v));
    return r;
}

// ---------------- small kernels ----------------
__global__ void k_init(float* out) {
    if (blockIdx.x == 0 && threadIdx.x == 0) out[0] = 0.0f;
}
__global__ void k_reset() {
    int i = blockIdx.x * 256 + threadIdx.x;
    if (i < NQ) g_mb[i] = 0x7F800000u;
}

// ---------------- fused 2-layer MLP via tf32 mma.sync ----------------
// Y[M,Nout] = relu(X[M,Kin] @ W1[Kin,HID] + b1) @ W2[HID,Nout] + b2
// CTA = 128 rows. 8 warps as 4(m) x 2(n); warp tile 32 x 64.
#define MP 132   // smem row pitch in floats
__global__ __launch_bounds__(256, 1)
void k_mlp(const float* __restrict__ X,  const float* __restrict__ W1,
           const float* __restrict__ B1, const float* __restrict__ W2,
           const float* __restrict__ B2, float* __restrict__ Y,
           int M, int Kin, int Nout)
{
    extern __shared__ __align__(16) uint32_t sm[];
    uint32_t* Xs  = sm;                  // [128][MP] : X (stage1 A), then H (stage2 A)
    uint32_t* W1t = Xs + 128 * MP;       // [n][k] transposed
    uint32_t* W2t = W1t + 128 * MP;      // [n][k] transposed
    int tid = threadIdx.x, lane = tid & 31, wid = tid >> 5;
    int warp_m = wid >> 1, warp_n = wid & 1;
    int m0 = blockIdx.x * 128;

    // zero all buffers (covers K/N padding)
    for (int i = tid; i < 3 * 128 * MP; i += 256) sm[i] = 0;
    __syncthreads();

    // load X tile (rows m0..m0+127, cols < Kin), tf32-converted
    for (int i = tid; i < 128 * Kin; i += 256) {
        int r = i / Kin, k = i - r * Kin;
        if (m0 + r < M) Xs[r * MP + k] = f2tf32(X[(size_t)(m0 + r) * Kin + k]);
    }
    // W1t[n][k] = W1[k][n]
    for (int i = tid; i < Kin * HID; i += 256) {
        int k = i / HID, n = i - k * HID;
        W1t[n * MP + k] = f2tf32(W1[i]);
    }
    // W2t[n][k] = W2[k][n]
    for (int i = tid; i < HID * Nout; i += 256) {
        int k = i / Nout, n = i - k * Nout;
        W2t[n * MP + k] = f2tf32(W2[i]);
    }
    __syncthreads();

    int r0 = lane >> 2, c0 = lane & 3;
    float acc[2][8][4];

    // ---------------- stage 1: H = relu(X @ W1 + b1) ----------------
#pragma unroll
    for (int mf = 0; mf < 2; mf++)
#pragma unroll
        for (int nf = 0; nf < 8; nf++)
#pragma unroll
            for (int r = 0; r < 4; r++) acc[mf][nf][r] = 0.0f;

    int ks1 = (Kin + 7) >> 3;
    for (int ks = 0; ks < ks1; ks++) {
        int kb = ks * 8;
        uint32_t a[2][4], b[8][2];
#pragma unroll
        for (int mf = 0; mf < 2; mf++) {
            int row = warp_m * 32 + mf * 16 + r0;
            const uint32_t* p = &Xs[row * MP + kb + c0];
            a[mf][0] = p[0];        a[mf][1] = p[8 * MP];
            a[mf][2] = p[4];        a[mf][3] = p[8 * MP + 4];
        }
#pragma unroll
        for (int nf = 0; nf < 8; nf++) {
            int col = warp_n * 64 + nf * 8 + r0;
            const uint32_t* p = &W1t[col * MP + kb + c0];
            b[nf][0] = p[0];        b[nf][1] = p[4];
        }
#pragma unroll
        for (int mf = 0; mf < 2; mf++)
#pragma unroll
            for (int nf = 0; nf < 8; nf++)
                asm volatile(
                    "mma.sync.aligned.m16n8k8.row.col.f32.tf32.tf32.f32 "
                    "{%0,%1,%2,%3}, {%4,%5,%6,%7}, {%8,%9}, {%0,%1,%2,%3};"
                    : "+f"(acc[mf][nf][0]), "+f"(acc[mf][nf][1]),
                      "+f"(acc[mf][nf][2]), "+f"(acc[mf][nf][3])
                    : "r"(a[mf][0]), "r"(a[mf][1]), "r"(a[mf][2]), "r"(a[mf][3]),
                      "r"(b[nf][0]), "r"(b[nf][1]));
    }
    __syncthreads();   // all warps done reading Xs

    // write H (relu + bias, tf32) back into Xs; cols >= HID forced to 0
#pragma unroll
    for (int mf = 0; mf < 2; mf++)
#pragma unroll
        for (int nf = 0; nf < 8; nf++) {
            int row = warp_m * 32 + mf * 16 + r0;
            int col = warp_n * 64 + nf * 8 + c0 * 2;
            float bi0 = (col < HID) ? B1[col] : 0.0f;
            float bi1 = (col + 1 < HID) ? B1[col + 1] : 0.0f;
            float v0 = (col < HID) ? fmaxf(acc[mf][nf][0] + bi0, 0.0f) : 0.0f;
            float v1 = (col + 1 < HID) ? fmaxf(acc[mf][nf][1] + bi1, 0.0f) : 0.0f;
            float v2 = (col < HID) ? fmaxf(acc[mf][nf][2] + bi0, 0.0f) : 0.0f;
            float v3 = (col + 1 < HID) ? fmaxf(acc[mf][nf][3] + bi1, 0.0f) : 0.0f;
            Xs[row * MP + col]           = f2tf32(v0);
            Xs[row * MP + col + 1]       = f2tf32(v1);
            Xs[(row + 8) * MP + col]     = f2tf32(v2);
            Xs[(row + 8) * MP + col + 1] = f2tf32(v3);
        }
    __syncthreads();

    // ---------------- stage 2: Y = H @ W2 + b2 ----------------
#pragma unroll
    for (int mf = 0; mf < 2; mf++)
#pragma unroll
        for (int nf = 0; nf < 8; nf++)
#pragma unroll
            for (int r = 0; r < 4; r++) acc[mf][nf][r] = 0.0f;

    int ks2 = (HID + 7) >> 3;
    for (int ks = 0; ks < ks2; ks++) {
        int kb = ks * 8;
        uint32_t a[2][4], b[8][2];
#pragma unroll
        for (int mf = 0; mf < 2; mf++) {
            int row = warp_m * 32 + mf * 16 + r0;
            const uint32_t* p = &Xs[row * MP + kb + c0];
            a[mf][0] = p[0];        a[mf][1] = p[8 * MP];
            a[mf][2] = p[4];        a[mf][3] = p[8 * MP + 4];
        }
#pragma unroll
        for (int nf = 0; nf < 8; nf++) {
            int col = warp_n * 64 + nf * 8 + r0;
            const uint32_t* p = &W2t[col * MP + kb + c0];
            b[nf][0] = p[0];        b[nf][1] = p[4];
        }
#pragma unroll
        for (int mf = 0; mf < 2; mf++)
#pragma unroll
            for (int nf = 0; nf < 8; nf++)
                asm volatile(
                    "mma.sync.aligned.m16n8k8.row.col.f32.tf32.tf32.f32 "
                    "{%0,%1,%2,%3}, {%4,%5,%6,%7}, {%8,%9}, {%0,%1,%2,%3};"
                    : "+f"(acc[mf][nf][0]), "+f"(acc[mf][nf][1]),
                      "+f"(acc[mf][nf][2]), "+f"(acc[mf][nf][3])
                    : "r"(a[mf][0]), "r"(a[mf][1]), "r"(a[mf][2]), "r"(a[mf][3]),
                      "r"(b[nf][0]), "r"(b[nf][1]));
    }

    // epilogue: bias + store (vectorized pairs)
#pragma unroll
    for (int mf = 0; mf < 2; mf++)
#pragma unroll
        for (int nf = 0; nf < 8; nf++) {
            int row = warp_m * 32 + mf * 16 + r0;
            int col = warp_n * 64 + nf * 8 + c0 * 2;
            if (col + 1 < Nout) {
                float bi0 = B2[col], bi1 = B2[col + 1];
                if (m0 + row < M) {
                    float2 v = make_float2(acc[mf][nf][0] + bi0, acc[mf][nf][1] + bi1);
                    *(float2*)&Y[(size_t)(m0 + row) * Nout + col] = v;
                }
                if (m0 + row + 8 < M) {
                    float2 v = make_float2(acc[mf][nf][2] + bi0, acc[mf][nf][3] + bi1);
                    *(float2*)&Y[(size_t)(m0 + row + 8) * Nout + col] = v;
                }
            }
        }
}

// ---------------- reductions ----------------
__global__ void k_rownorm_diff(const float* __restrict__ A, const float* __restrict__ B,
                               int M, int Kc, float scale, float* out)
{
    int w = threadIdx.x >> 5, lane = threadIdx.x & 31;
    int row = blockIdx.x * 8 + w;
    float r = 0.0f;
    if (row < M) {
        const float* a = A + (size_t)row * Kc;
        const float* b = B + (size_t)row * Kc;
        float s = 0.0f;
        for (int j = lane; j < Kc; j += 32) { float d = a[j] - b[j]; s = fmaf(d, d, s); }
#pragma unroll
        for (int o = 16; o; o >>= 1) s += __shfl_xor_sync(0xffffffffu, s, o);
        r = sqrtf(s);
    }
    __shared__ float sh[8];
    if (lane == 0) sh[w] = r;
    __syncthreads();
    if (threadIdx.x == 0) {
        float t = 0.0f;
#pragma unroll
        for (int i = 0; i < 8; i++) t += sh[i];
        atomicAdd(out, t * scale);
    }
}

__global__ void k_rownorm_sup(const float* __restrict__ A, const float* __restrict__ B,
                              const int* __restrict__ imap, int Kc, int aSel,
                              float scale, float* out)
{
    int w = threadIdx.x >> 5, lane = threadIdx.x & 31;
    int i = blockIdx.x * 8 + w;
    float r = 0.0f;
    if (i < NQ) {
        const float* a = A + (size_t)imap[2 * i + aSel] * Kc;
        const float* b = B + (size_t)imap[2 * i + 1 - aSel] * Kc;
        float s = 0.0f;
        for (int j = lane; j < Kc; j += 32) { float d = a[j] - b[j]; s = fmaf(d, d, s); }
#pragma unroll
        for (int o = 16; o; o >>= 1) s += __shfl_xor_sync(0xffffffffu, s, o);
        r = sqrtf(s);
    }
    __shared__ float sh[8];
    if (lane == 0) sh[w] = r;
    __syncthreads();
    if (threadIdx.x == 0) {
        float t = 0.0f;
#pragma unroll
        for (int k = 0; k < 8; k++) t += sh[k];
        atomicAdd(out, t * scale);
    }
}

__global__ void k_tnorm(const float* __restrict__ T, int M, int Kc, float* __restrict__ tn)
{
    int w = threadIdx.x >> 5, lane = threadIdx.x & 31;
    int row = blockIdx.x * 8 + w;
    if (row >= M) return;
    const float* a = T + (size_t)row * Kc;
    float s = 0.0f;
    for (int j = lane; j < Kc; j += 32) s = fmaf(a[j], a[j], s);
#pragma unroll
    for (int o = 16; o; o >>= 1) s += __shfl_xor_sync(0xffffffffu, s, o);
    if (lane == 0) tn[row] = s;
}

// ---------------- bf16 prep ----------------
__global__ void k_prep_t(const float* __restrict__ T, const float* __restrict__ tn, int K)
{
    int idx = blockIdx.x * 256 + threadIdx.x;
    if (idx >= NTPAD * KP) return;
    int row = idx >> 7, col = idx & 127;
    float v = 0.0f;
    if (row < NROWS) {
        if (col < K) v = T[(size_t)row * K + col];
        else if (col == K) v = CSHIFT + tn[row];
        else if (col == K + 1) {
            float s = CSHIFT + tn[row];
            v = s - __bfloat162float(__float2bfloat16(s));
        }
    } else if (col == K) v = 1.0e6f;
    g_Tb[idx] = __float2bfloat16(v);
}
__global__ void k_prep_q(const float* __restrict__ mapped, const int* __restrict__ imap,
                         int sel, int K)
{
    int idx = blockIdx.x * 256 + threadIdx.x;
    if (idx >= NQPAD * KP) return;
    int row = idx >> 7, col = idx & 127;
    float v = 0.0f;
    if (row < NQ) {
        if (col < K) v = -2.0f * mapped[(size_t)imap[2 * row + sel] * K + col];
        else if (col <= K + 1) v = 1.0f;
    }
    g_Qb[idx] = __float2bfloat16(v);
}

__global__ void k_pref(const int* __restrict__ imap, int sel)
{
    int w = threadIdx.x >> 5, lane = threadIdx.x & 31;
    int q = blockIdx.x * 8 + w;
    if (q >= NQ) return;
    int t = imap[2 * q + sel];
    const __nv_bfloat16* qr = g_Qb + (size_t)q * KP;
    const __nv_bfloat16* tr = g_Tb + (size_t)t * KP;
    float s = 0.0f;
#pragma unroll
    for (int k = lane; k < KP; k += 32)
        s = fmaf(__bfloat162float(qr[k]), __bfloat162float(tr[k]), s);
#pragma unroll
    for (int o = 16; o; o >>= 1) s += __shfl_xor_sync(0xffffffffu, s, o);
    if (lane == 0) g_pref[q] = s;
}

// ---------------- mma.sync 1-NN proxy-min ----------------
#define PITCH_B 272
#define SM_B0   (128 * PITCH_B)
#define SM_B1   (SM_B0 + 128 * PITCH_B)
#define SM_MIN  (SM_B1 + 128 * PITCH_B)
#define SMEM_NN (SM_MIN + 512)

__global__ __launch_bounds__(256, 2)
void k_nn(const char* __restrict__ Qb, const char* __restrict__ Tb)
{
    extern __shared__ __align__(16) char dsm[];
    uint32_t sbase = smem_u32(dsm);
    unsigned* smin = (unsigned*)(dsm + SM_MIN);
    int tid = threadIdx.x, lane = tid & 31, wid = tid >> 5;
    int warp_m = wid >> 2, warp_n = wid & 3;
    int qtile = blockIdx.x, g = blockIdx.y;

    {
        const char* Ag = Qb + (size_t)qtile * 32768;
        const char* Bg = Tb + (size_t)(g * NCH_PER) * 32768;
        for (int i = tid; i < 2048; i += 256) {
            int row = i >> 4, c16 = (i & 15) * 16;
            cpa16(sbase + row * PITCH_B + c16, Ag + row * 256 + c16);
            cpa16(sbase + SM_B0 + row * PITCH_B + c16, Bg + row * 256 + c16);
        }
        CP_COMMIT();
    }
    if (tid < 128) smin[tid] = 0x7F800000u;

    float best0[4], best1[4];
#pragma unroll
    for (int mf = 0; mf < 4; mf++) { best0[mf] = 1e30f; best1[mf] = 1e30f; }

    uint32_t aAddr = sbase + (uint32_t)((warp_m * 64 + (lane & 15)) * PITCH_B
                                        + ((lane >> 4) & 1) * 16);
    uint32_t bOff  = (uint32_t)((warp_n * 32 + (lane & 7)) * PITCH_B
                                + ((lane >> 3) & 1) * 16);

    for (int c = 0; c < NCH_PER; c++) {
        CP_WAIT0();
        __syncthreads();
        if (c + 1 < NCH_PER) {
            const char* Bg = Tb + (size_t)(g * NCH_PER + c + 1) * 32768;
            uint32_t dstb = sbase + (((c + 1) & 1) ? SM_B1 : SM_B0);
            for (int i = tid; i < 2048; i += 256) {
                int row = i >> 4, c16 = (i & 15) * 16;
                cpa16(dstb + row * PITCH_B + c16, Bg + row * 256 + c16);
            }
            CP_COMMIT();
        }
        uint32_t bAddr = sbase + ((c & 1) ? SM_B1 : SM_B0) + bOff;

        float acc[4][4][4];
#pragma unroll
        for (int mf = 0; mf < 4; mf++)
#pragma unroll
            for (int nf = 0; nf < 4; nf++)
#pragma unroll
                for (int r = 0; r < 4; r++) acc[mf][nf][r] = 0.0f;

#pragma unroll
        for (int ks = 0; ks < 8; ks++) {
            uint32_t a[4][4], b[4][2];
#pragma unroll
            for (int mf = 0; mf < 4; mf++)
                asm volatile(
                    "ldmatrix.sync.aligned.m8n8.x4.shared.b16 {%0,%1,%2,%3}, [%4];"
                    : "=r"(a[mf][0]), "=r"(a[mf][1]), "=r"(a[mf][2]), "=r"(a[mf][3])
                    : "r"(aAddr + mf * 16 * PITCH_B + ks * 32));
#pragma unroll
            for (int nf = 0; nf < 4; nf++)
                asm volatile(
                    "ldmatrix.sync.aligned.m8n8.x2.shared.b16 {%0,%1}, [%2];"
                    : "=r"(b[nf][0]), "=r"(b[nf][1])
                    : "r"(bAddr + nf * 8 * PITCH_B + ks * 32));
#pragma unroll
            for (int mf = 0; mf < 4; mf++)
#pragma unroll
                for (int nf = 0; nf < 4; nf++)
                    asm volatile(
                        "mma.sync.aligned.m16n8k16.row.col.f32.bf16.bf16.f32 "
                        "{%0,%1,%2,%3}, {%4,%5,%6,%7}, {%8,%9}, {%0,%1,%2,%3};"
                        : "+f"(acc[mf][nf][0]), "+f"(acc[mf][nf][1]),
                          "+f"(acc[mf][nf][2]), "+f"(acc[mf][nf][3])
                        : "r"(a[mf][0]), "r"(a[mf][1]), "r"(a[mf][2]), "r"(a[mf][3]),
                          "r"(b[nf][0]), "r"(b[nf][1]));
        }
#pragma unroll
        for (int mf = 0; mf < 4; mf++)
#pragma unroll
            for (int nf = 0; nf < 4; nf++) {
                best0[mf] = fminf(best0[mf], fminf(acc[mf][nf][0], acc[mf][nf][1]));
                best1[mf] = fminf(best1[mf], fminf(acc[mf][nf][2], acc[mf][nf][3]));
            }
    }

#pragma unroll
    for (int mf = 0; mf < 4; mf++) {
        float v0 = best0[mf], v1 = best1[mf];
        v0 = fminf(v0, __shfl_xor_sync(0xffffffffu, v0, 1));
        v0 = fminf(v0, __shfl_xor_sync(0xffffffffu, v0, 2));
        v1 = fminf(v1, __shfl_xor_sync(0xffffffffu, v1, 1));
        v1 = fminf(v1, __shfl_xor_sync(0xffffffffu, v1, 2));
        if ((lane & 3) == 0) {
            int r = warp_m * 64 + mf * 16 + (lane >> 2);
            atomicMin(&smin[r], __float_as_uint(v0));
            atomicMin(&smin[r + 8], __float_as_uint(v1));
        }
    }
    __syncthreads();
    if (tid < 128) {
        int q = qtile * 128 + tid;
        if (q < NQ) atomicMin(&g_mb[q], smin[tid]);
    }
}

// ---------------- finalize mismatch ----------------
__global__ void k_finish_nn(float scale, float* out)
{
    __shared__ float sh[256];
    int i = blockIdx.x * 256 + threadIdx.x;
    float c = 0.0f;
    if (i < NQ) {
        float m = __uint_as_float(g_mb[i]);
        if (m < g_pref[i] - 1e-4f) c = 1.0f;
    }
    sh[threadIdx.x] = c;
    __syncthreads();
    for (int s = 128; s; s >>= 1) {
        if (threadIdx.x < s) sh[threadIdx.x] += sh[threadIdx.x + s];
        __syncthreads();
    }
    if (threadIdx.x == 0) atomicAdd(out, sh[0] * scale);
}

// ---------------- host ----------------
extern "C" void kernel_launch(void* const* d_in, const int* in_sizes, int n_in,
                              void* d_out, int out_size)
{
    const float* x_w   = (const float*)d_in[0];
    const float* y_w   = (const float*)d_in[1];
    const float* fx_w1 = (const float*)d_in[2];
    const float* fx_b1 = (const float*)d_in[3];
    const float* fx_w2 = (const float*)d_in[4];
    const float* fx_b2 = (const float*)d_in[5];
    const float* gy_w1 = (const float*)d_in[6];
    const float* gy_b1 = (const float*)d_in[7];
    const float* gy_w2 = (const float*)d_in[8];
    const float* gy_b2 = (const float*)d_in[9];
    const int*   imap  = (const int*)d_in[10];
    float* out = (float*)d_out;

    float *xmap, *ymap, *xrt, *yrt, *tnY, *tnX;
    char *Qb, *Tb;
    cudaGetSymbolAddress((void**)&xmap, g_xmap);
    cudaGetSymbolAddress((void**)&ymap, g_ymap);
    cudaGetSymbolAddress((void**)&xrt,  g_xrt);
    cudaGetSymbolAddress((void**)&yrt,  g_yrt);
    cudaGetSymbolAddress((void**)&tnY,  g_tnY);
    cudaGetSymbolAddress((void**)&tnX,  g_tnX);
    cudaGetSymbolAddress((void**)&Qb,   g_Qb);
    cudaGetSymbolAddress((void**)&Tb,   g_Tb);

    static int smemSet = 0;
    if (!smemSet) {
        cudaFuncSetAttribute(k_nn, cudaFuncAttributeMaxDynamicSharedMemorySize, SMEM_NN);
        cudaFuncSetAttribute(k_mlp, cudaFuncAttributeMaxDynamicSharedMemorySize,
                             3 * 128 * MP * 4);
        smemSet = 1;
    }

    k_init<<<1, 32>>>(out);

    int mlpGrid = (NROWS + 127) / 128;
    int mlpSmem = 3 * 128 * MP * 4;
    k_mlp<<<mlpGrid, 256, mlpSmem>>>(x_w,  fx_w1, fx_b1, fx_w2, fx_b2, xmap, NROWS, XD, YD);
    k_mlp<<<mlpGrid, 256, mlpSmem>>>(y_w,  gy_w1, gy_b1, gy_w2, gy_b2, ymap, NROWS, YD, XD);
    k_mlp<<<mlpGrid, 256, mlpSmem>>>(xmap, gy_w1, gy_b1, gy_w2, gy_b2, xrt,  NROWS, YD, XD);
    k_mlp<<<mlpGrid, 256, mlpSmem>>>(ymap, fx_w1, fx_b1, fx_w2, fx_b2, yrt,  NROWS, XD, YD);

    k_rownorm_diff<<<(NROWS + 7) / 8, 256>>>(xrt, x_w, NROWS, XD, 1.0f / NROWS, out);
    k_rownorm_diff<<<(NROWS + 7) / 8, 256>>>(yrt, y_w, NROWS, YD, 1.0f / NROWS, out);
    k_rownorm_sup<<<(NQ + 7) / 8, 256>>>(xmap, y_w, imap, YD, 0, 1.0f / NQ, out);
    k_rownorm_sup<<<(NQ + 7) / 8, 256>>>(ymap, x_w, imap, XD, 1, 1.0f / NQ, out);

    k_tnorm<<<(NROWS + 7) / 8, 256>>>(y_w, NROWS, YD, tnY);
    k_tnorm<<<(NROWS + 7) / 8, 256>>>(x_w, NROWS, XD, tnX);

    dim3 ng(QTILES, GSPLIT);
    // side A: queries = x_mapped[imap0], targets = y_weight
    k_prep_t<<<(NTPAD * KP + 255) / 256, 256>>>(y_w, tnY, YD);
    k_prep_q<<<(NQPAD * KP + 255) / 256, 256>>>(xmap, imap, 0, YD);
    k_reset<<<(NQ + 255) / 256, 256>>>();
    k_pref<<<(NQ + 7) / 8, 256>>>(imap, 0);
    k_nn<<<ng, 256, SMEM_NN>>>(Qb, Tb);
    k_finish_nn<<<(NQ + 255) / 256, 256>>>(1.0f / NQ, out);
    // side B: queries = y_mapped[imap1], targets = x_weight
    k_prep_t<<<(NTPAD * KP + 255) / 256, 256>>>(x_w, tnX, XD);
    k_prep_q<<<(NQPAD * KP + 255) / 256, 256>>>(ymap, imap, 1, XD);
    k_reset<<<(NQ + 255) / 256, 256>>>();
    k_pref<<<(NQ + 7) / 8, 256>>>(imap, 1);
    k_nn<<<ng, 256, SMEM_NN>>>(Qb, Tb);
    k_finish_nn<<<(NQ + 255) / 256, 256>>>(1.0f / NQ, out);
}

// round 7
// speedup vs baseline: 7.3861x; 1.2739x over previous
#include <cuda_runtime.h>
#include <cuda_bf16.h>
#include <math.h>
#include <stdint.h>

// ---------------- problem constants ----------------
#define NROWS 25000
#define NQ    8000
#define XD    100
#define YD    120
#define HID   100
#define KP    128
#define NQPAD 8064          // 63*128
#define NTPAD 25088         // 196*128
#define QTILES 63
#define GSPLIT 14
#define NCH_PER 14
#define CSHIFT 8.0f
#define MP    132           // MLP smem/weight pitch (floats)
#define WSTRIDE (128 * MP)  // 16896 words per weight matrix
#define XPAD_ROWS 25088

// ---------------- scratch ----------------
__device__ float g_xmap[NROWS * YD];
__device__ float g_ymap[NROWS * XD];
__device__ float g_xrt [NROWS * XD];
__device__ float g_yrt [NROWS * YD];
__device__ float g_tnY [NROWS];
__device__ float g_tnX [NROWS];
__device__ uint32_t g_Wt[4 * WSTRIDE];            // tf32 transposed weights
__device__ float g_Xpad[2 * XPAD_ROWS * 128];     // padded tf32 inputs, 2 slots
__device__ __align__(16) __nv_bfloat16 g_QbA[NQPAD * KP];
__device__ __align__(16) __nv_bfloat16 g_QbB[NQPAD * KP];
__device__ __align__(16) __nv_bfloat16 g_TbA[NTPAD * KP];
__device__ __align__(16) __nv_bfloat16 g_TbB[NTPAD * KP];
__device__ unsigned int g_mbA[NQ];
__device__ unsigned int g_mbB[NQ];
__device__ float g_prefA[NQ];
__device__ float g_prefB[NQ];

// ---------------- helpers ----------------
__device__ __forceinline__ uint32_t smem_u32(const void* p) {
    uint32_t a;
    asm("{ .reg .u64 t; cvta.to.shared.u64 t, %1; cvt.u32.u64 %0, t; }" : "=r"(a) : "l"(p));
    return a;
}
__device__ __forceinline__ void cpa16(uint32_t dst, const void* src) {
    asm volatile("cp.async.cg.shared.global [%0], [%1], 16;" :: "r"(dst), "l"(src));
}
#define CP_COMMIT() asm volatile("cp.async.commit_group;" ::: "memory")
#define CP_WAIT0()  asm volatile("cp.async.wait_group 0;" ::: "memory")

__device__ __forceinline__ uint32_t f2tf32(float v) {
    uint32_t r;
    asm("cvt.rna.tf32.f32 %0, %1;" : "=r"(r) : "f"(v));
    return r;
}

// ---------------- init (out + mb resets) ----------------
__global__ void k_init(float* out) {
    int i = blockIdx.x * 256 + threadIdx.x;
    if (i == 0) out[0] = 0.0f;
    if (i < NQ) { g_mbA[i] = 0x7F800000u; g_mbB[i] = 0x7F800000u; }
}

// ---------------- weight prep: 4 matrices -> transposed padded tf32 ----------
// slots: 0=fx_w1(XD,HID) 1=fx_w2(HID,YD) 2=gy_w1(YD,HID) 3=gy_w2(HID,XD)
__global__ void k_wprep(const float* __restrict__ w0, const float* __restrict__ w1,
                        const float* __restrict__ w2, const float* __restrict__ w3)
{
    int idx = blockIdx.x * 256 + threadIdx.x;
    if (idx >= 4 * WSTRIDE) return;
    int m = idx / WSTRIDE, r = idx - m * WSTRIDE;
    int n = r / MP, k = r - n * MP;
    const float* src; int Kd, Nd;
    if (m == 0)      { src = w0; Kd = XD;  Nd = HID; }
    else if (m == 1) { src = w1; Kd = HID; Nd = YD;  }
    else if (m == 2) { src = w2; Kd = YD;  Nd = HID; }
    else             { src = w3; Kd = HID; Nd = XD;  }
    float v = (n < Nd && k < Kd) ? src[k * Nd + n] : 0.0f;
    g_Wt[idx] = f2tf32(v);
}

// ---------------- input pad: [NROWS][Kin] -> [25088][128] tf32 ---------------
__global__ void k_xpad(const float* __restrict__ x0, const float* __restrict__ x1,
                       int K0, int K1)
{
    int z = blockIdx.y;
    int idx = blockIdx.x * 256 + threadIdx.x;   // over 25088*128
    int row = idx >> 7, col = idx & 127;
    const float* src = z ? x1 : x0;
    int Kin = z ? K1 : K0;
    float v = (row < NROWS && col < Kin) ? src[(size_t)row * Kin + col] : 0.0f;
    g_Xpad[(size_t)z * (XPAD_ROWS * 128) + idx] = __uint_as_float(f2tf32(v));
}

// ---------------- fused 2-layer MLP (2 problems per launch via z) ------------
__global__ __launch_bounds__(256, 1)
void k_mlp2(int wsel0, int wsel1,
            const float* __restrict__ b1_0, const float* __restrict__ b2_0,
            const float* __restrict__ b1_1, const float* __restrict__ b2_1,
            float* __restrict__ Y0, float* __restrict__ Y1,
            int Kin0, int Nout0, int Kin1, int Nout1, int writePad)
{
    extern __shared__ __align__(16) uint32_t sm[];
    uint32_t* Xs  = sm;
    uint32_t* W1t = Xs + 128 * MP;
    uint32_t* W2t = W1t + 128 * MP;
    int tid = threadIdx.x, lane = tid & 31, wid = tid >> 5;
    int warp_m = wid >> 1, warp_n = wid & 1;
    int z = blockIdx.y;
    int m0 = blockIdx.x * 128;

    int wsel = z ? wsel1 : wsel0;
    int Kin  = z ? Kin1 : Kin0;
    int Nout = z ? Nout1 : Nout0;
    const float* B1 = z ? b1_1 : b1_0;
    const float* B2 = z ? b2_1 : b2_0;
    float* Y = z ? Y1 : Y0;
    float* Xpad = g_Xpad + (size_t)z * (XPAD_ROWS * 128);

    // prologue: pure cp.async (no conversion, no zeroing)
    {
        uint32_t sX = smem_u32(Xs);
        const float* xsrc = Xpad + (size_t)m0 * 128;
        for (int i = tid; i < 4096; i += 256) {           // 128 rows x 32 chunks
            int r = i >> 5, c = i & 31;
            cpa16(sX + r * (MP * 4) + c * 16, xsrc + r * 128 + c * 4);
        }
        uint32_t sW = smem_u32(W1t);
        const char* wsrc = (const char*)(g_Wt + wsel * 2 * WSTRIDE);
        for (int i = tid; i < 8448; i += 256)             // W1t+W2t contiguous
            cpa16(sW + i * 16, wsrc + i * 16);
        CP_COMMIT();
        CP_WAIT0();
    }
    __syncthreads();

    int r0 = lane >> 2, c0 = lane & 3;
    float acc[2][8][4];
    int nf1max = warp_n ? 5 : 8;                          // HID=100: cols>=104 dead
    int nf2max = warp_n ? ((Nout > 104) ? 7 : 5) : 8;

    // ---------------- stage 1 ----------------
#pragma unroll
    for (int mf = 0; mf < 2; mf++)
#pragma unroll
        for (int nf = 0; nf < 8; nf++)
#pragma unroll
            for (int r = 0; r < 4; r++) acc[mf][nf][r] = 0.0f;

    int ks1 = (Kin + 7) >> 3;
    for (int ks = 0; ks < ks1; ks++) {
        int kb = ks * 8;
        uint32_t a[2][4], b[8][2];
#pragma unroll
        for (int mf = 0; mf < 2; mf++) {
            int row = warp_m * 32 + mf * 16 + r0;
            const uint32_t* p = &Xs[row * MP + kb + c0];
            a[mf][0] = p[0]; a[mf][1] = p[8 * MP]; a[mf][2] = p[4]; a[mf][3] = p[8 * MP + 4];
        }
#pragma unroll
        for (int nf = 0; nf < 8; nf++) {
            if (nf < nf1max) {
                int col = warp_n * 64 + nf * 8 + r0;
                const uint32_t* p = &W1t[col * MP + kb + c0];
                b[nf][0] = p[0]; b[nf][1] = p[4];
            }
        }
#pragma unroll
        for (int mf = 0; mf < 2; mf++)
#pragma unroll
            for (int nf = 0; nf < 8; nf++)
                if (nf < nf1max)
                    asm volatile(
                        "mma.sync.aligned.m16n8k8.row.col.f32.tf32.tf32.f32 "
                        "{%0,%1,%2,%3}, {%4,%5,%6,%7}, {%8,%9}, {%0,%1,%2,%3};"
                        : "+f"(acc[mf][nf][0]), "+f"(acc[mf][nf][1]),
                          "+f"(acc[mf][nf][2]), "+f"(acc[mf][nf][3])
                        : "r"(a[mf][0]), "r"(a[mf][1]), "r"(a[mf][2]), "r"(a[mf][3]),
                          "r"(b[nf][0]), "r"(b[nf][1]));
    }
    __syncthreads();

    // H = relu(acc + b1), tf32, back into Xs (cols >= HID zeroed)
#pragma unroll
    for (int mf = 0; mf < 2; mf++)
#pragma unroll
        for (int nf = 0; nf < 8; nf++) {
            int row = warp_m * 32 + mf * 16 + r0;
            int col = warp_n * 64 + nf * 8 + c0 * 2;
            float bi0 = (col < HID) ? B1[col] : 0.0f;
            float bi1 = (col + 1 < HID) ? B1[col + 1] : 0.0f;
            float v0 = (col < HID) ? fmaxf(acc[mf][nf][0] + bi0, 0.0f) : 0.0f;
            float v1 = (col + 1 < HID) ? fmaxf(acc[mf][nf][1] + bi1, 0.0f) : 0.0f;
            float v2 = (col < HID) ? fmaxf(acc[mf][nf][2] + bi0, 0.0f) : 0.0f;
            float v3 = (col + 1 < HID) ? fmaxf(acc[mf][nf][3] + bi1, 0.0f) : 0.0f;
            Xs[row * MP + col]           = f2tf32(v0);
            Xs[row * MP + col + 1]       = f2tf32(v1);
            Xs[(row + 8) * MP + col]     = f2tf32(v2);
            Xs[(row + 8) * MP + col + 1] = f2tf32(v3);
        }
    __syncthreads();

    // ---------------- stage 2 ----------------
#pragma unroll
    for (int mf = 0; mf < 2; mf++)
#pragma unroll
        for (int nf = 0; nf < 8; nf++)
#pragma unroll
            for (int r = 0; r < 4; r++) acc[mf][nf][r] = 0.0f;

    int ks2 = (HID + 7) >> 3;
    for (int ks = 0; ks < ks2; ks++) {
        int kb = ks * 8;
        uint32_t a[2][4], b[8][2];
#pragma unroll
        for (int mf = 0; mf < 2; mf++) {
            int row = warp_m * 32 + mf * 16 + r0;
            const uint32_t* p = &Xs[row * MP + kb + c0];
            a[mf][0] = p[0]; a[mf][1] = p[8 * MP]; a[mf][2] = p[4]; a[mf][3] = p[8 * MP + 4];
        }
#pragma unroll
        for (int nf = 0; nf < 8; nf++) {
            if (nf < nf2max) {
                int col = warp_n * 64 + nf * 8 + r0;
                const uint32_t* p = &W2t[col * MP + kb + c0];
                b[nf][0] = p[0]; b[nf][1] = p[4];
            }
        }
#pragma unroll
        for (int mf = 0; mf < 2; mf++)
#pragma unroll
            for (int nf = 0; nf < 8; nf++)
                if (nf < nf2max)
                    asm volatile(
                        "mma.sync.aligned.m16n8k8.row.col.f32.tf32.tf32.f32 "
                        "{%0,%1,%2,%3}, {%4,%5,%6,%7}, {%8,%9}, {%0,%1,%2,%3};"
                        : "+f"(acc[mf][nf][0]), "+f"(acc[mf][nf][1]),
                          "+f"(acc[mf][nf][2]), "+f"(acc[mf][nf][3])
                        : "r"(a[mf][0]), "r"(a[mf][1]), "r"(a[mf][2]), "r"(a[mf][3]),
                          "r"(b[nf][0]), "r"(b[nf][1]));
    }

    // epilogue: bias + store Y (+ padded tf32 for next stage)
#pragma unroll
    for (int mf = 0; mf < 2; mf++)
#pragma unroll
        for (int nf = 0; nf < 8; nf++) {
            int row = warp_m * 32 + mf * 16 + r0;
            int col = warp_n * 64 + nf * 8 + c0 * 2;
            bool cok = (col + 1 < Nout) | (col + 1 == Nout);  // Nout even -> pair ok iff col<Nout
            float bi0 = (col < Nout) ? B2[col] : 0.0f;
            float bi1 = (col + 1 < Nout) ? B2[col + 1] : 0.0f;
            float v0 = (col < Nout) ? acc[mf][nf][0] + bi0 : 0.0f;
            float v1 = (col + 1 < Nout) ? acc[mf][nf][1] + bi1 : 0.0f;
            float v2 = (col < Nout) ? acc[mf][nf][2] + bi0 : 0.0f;
            float v3 = (col + 1 < Nout) ? acc[mf][nf][3] + bi1 : 0.0f;
            if (m0 + row < NROWS) {
                if (col < Nout && cok)
                    *(float2*)&Y[(size_t)(m0 + row) * Nout + col] = make_float2(v0, v1);
                if (writePad)
                    *(float2*)&Xpad[(size_t)(m0 + row) * 128 + col] =
                        make_float2(__uint_as_float(f2tf32(v0)), __uint_as_float(f2tf32(v1)));
            }
            if (m0 + row + 8 < NROWS) {
                if (col < Nout && cok)
                    *(float2*)&Y[(size_t)(m0 + row + 8) * Nout + col] = make_float2(v2, v3);
                if (writePad)
                    *(float2*)&Xpad[(size_t)(m0 + row + 8) * 128 + col] =
                        make_float2(__uint_as_float(f2tf32(v2)), __uint_as_float(f2tf32(v3)));
            }
        }
}

// ---------------- fused reductions ----------------
__global__ void k_rnd(const float* __restrict__ A0, const float* __restrict__ B0, int K0,
                      const float* __restrict__ A1, const float* __restrict__ B1, int K1,
                      float scale, float* out)
{
    int z = blockIdx.y;
    const float* A = z ? A1 : A0; const float* B = z ? B1 : B0;
    int Kc = z ? K1 : K0;
    int w = threadIdx.x >> 5, lane = threadIdx.x & 31;
    int row = blockIdx.x * 8 + w;
    float r = 0.0f;
    if (row < NROWS) {
        const float* a = A + (size_t)row * Kc;
        const float* b = B + (size_t)row * Kc;
        float s = 0.0f;
        for (int j = lane; j < Kc; j += 32) { float d = a[j] - b[j]; s = fmaf(d, d, s); }
#pragma unroll
        for (int o = 16; o; o >>= 1) s += __shfl_xor_sync(0xffffffffu, s, o);
        r = sqrtf(s);
    }
    __shared__ float sh[8];
    if (lane == 0) sh[w] = r;
    __syncthreads();
    if (threadIdx.x == 0) {
        float t = 0.0f;
#pragma unroll
        for (int i = 0; i < 8; i++) t += sh[i];
        atomicAdd(out, t * scale);
    }
}

__global__ void k_sup(const float* __restrict__ A0, const float* __restrict__ B0, int K0,
                      const float* __restrict__ A1, const float* __restrict__ B1, int K1,
                      const int* __restrict__ imap, float scale, float* out)
{
    int z = blockIdx.y;
    const float* A = z ? A1 : A0; const float* B = z ? B1 : B0;
    int Kc = z ? K1 : K0; int aSel = z;
    int w = threadIdx.x >> 5, lane = threadIdx.x & 31;
    int i = blockIdx.x * 8 + w;
    float r = 0.0f;
    if (i < NQ) {
        const float* a = A + (size_t)imap[2 * i + aSel] * Kc;
        const float* b = B + (size_t)imap[2 * i + 1 - aSel] * Kc;
        float s = 0.0f;
        for (int j = lane; j < Kc; j += 32) { float d = a[j] - b[j]; s = fmaf(d, d, s); }
#pragma unroll
        for (int o = 16; o; o >>= 1) s += __shfl_xor_sync(0xffffffffu, s, o);
        r = sqrtf(s);
    }
    __shared__ float sh[8];
    if (lane == 0) sh[w] = r;
    __syncthreads();
    if (threadIdx.x == 0) {
        float t = 0.0f;
#pragma unroll
        for (int k = 0; k < 8; k++) t += sh[k];
        atomicAdd(out, t * scale);
    }
}

__global__ void k_tnf(const float* __restrict__ T0, int K0, const float* __restrict__ T1, int K1)
{
    int z = blockIdx.y;
    const float* T = z ? T1 : T0; int Kc = z ? K1 : K0;
    float* tn = z ? g_tnX : g_tnY;
    int w = threadIdx.x >> 5, lane = threadIdx.x & 31;
    int row = blockIdx.x * 8 + w;
    if (row >= NROWS) return;
    const float* a = T + (size_t)row * Kc;
    float s = 0.0f;
    for (int j = lane; j < Kc; j += 32) s = fmaf(a[j], a[j], s);
#pragma unroll
    for (int o = 16; o; o >>= 1) s += __shfl_xor_sync(0xffffffffu, s, o);
    if (lane == 0) tn[row] = s;
}

// ---------------- bf16 NN preps (fused z) ----------------
__global__ void k_prep_t(const float* __restrict__ T0, int K0,
                         const float* __restrict__ T1, int K1)
{
    int z = blockIdx.y;
    const float* T = z ? T1 : T0; int K = z ? K1 : K0;
    const float* tn = z ? g_tnX : g_tnY;
    __nv_bfloat16* Tb = z ? g_TbB : g_TbA;
    int idx = blockIdx.x * 256 + threadIdx.x;
    if (idx >= NTPAD * KP) return;
    int row = idx >> 7, col = idx & 127;
    float v = 0.0f;
    if (row < NROWS) {
        if (col < K) v = T[(size_t)row * K + col];
        else if (col == K) v = CSHIFT + tn[row];
        else if (col == K + 1) {
            float s = CSHIFT + tn[row];
            v = s - __bfloat162float(__float2bfloat16(s));
        }
    } else if (col == K) v = 1.0e6f;
    Tb[idx] = __float2bfloat16(v);
}

__global__ void k_prep_q(const float* __restrict__ m0, int K0,
                         const float* __restrict__ m1, int K1,
                         const int* __restrict__ imap)
{
    int z = blockIdx.y;
    const float* mapped = z ? m1 : m0; int K = z ? K1 : K0; int sel = z;
    __nv_bfloat16* Qb = z ? g_QbB : g_QbA;
    int idx = blockIdx.x * 256 + threadIdx.x;
    if (idx >= NQPAD * KP) return;
    int row = idx >> 7, col = idx & 127;
    float v = 0.0f;
    if (row < NQ) {
        if (col < K) v = -2.0f * mapped[(size_t)imap[2 * row + sel] * K + col];
        else if (col <= K + 1) v = 1.0f;
    }
    Qb[idx] = __float2bfloat16(v);
}

__global__ void k_pref(const int* __restrict__ imap)
{
    int z = blockIdx.y;
    const __nv_bfloat16* Qb = z ? g_QbB : g_QbA;
    const __nv_bfloat16* Tb = z ? g_TbB : g_TbA;
    float* pref = z ? g_prefB : g_prefA;
    int w = threadIdx.x >> 5, lane = threadIdx.x & 31;
    int q = blockIdx.x * 8 + w;
    if (q >= NQ) return;
    int t = imap[2 * q + z];
    const __nv_bfloat16* qr = Qb + (size_t)q * KP;
    const __nv_bfloat16* tr = Tb + (size_t)t * KP;
    float s = 0.0f;
#pragma unroll
    for (int k = lane; k < KP; k += 32)
        s = fmaf(__bfloat162float(qr[k]), __bfloat162float(tr[k]), s);
#pragma unroll
    for (int o = 16; o; o >>= 1) s += __shfl_xor_sync(0xffffffffu, s, o);
    if (lane == 0) pref[q] = s;
}

// ---------------- mma.sync 1-NN proxy-min (both sides via z) ----------------
#define PITCH_B 272
#define SM_B0   (128 * PITCH_B)
#define SM_B1   (SM_B0 + 128 * PITCH_B)
#define SM_MIN  (SM_B1 + 128 * PITCH_B)
#define SMEM_NN (SM_MIN + 512)

__global__ __launch_bounds__(256, 2)
void k_nn()
{
    extern __shared__ __align__(16) char dsm[];
    uint32_t sbase = smem_u32(dsm);
    unsigned* smin = (unsigned*)(dsm + SM_MIN);
    int tid = threadIdx.x, lane = tid & 31, wid = tid >> 5;
    int warp_m = wid >> 2, warp_n = wid & 3;
    int qtile = blockIdx.x, g = blockIdx.y, z = blockIdx.z;
    const char* Qb = z ? (const char*)g_QbB : (const char*)g_QbA;
    const char* Tb = z ? (const char*)g_TbB : (const char*)g_TbA;
    unsigned* mb = z ? g_mbB : g_mbA;

    {
        const char* Ag = Qb + (size_t)qtile * 32768;
        const char* Bg = Tb + (size_t)(g * NCH_PER) * 32768;
        for (int i = tid; i < 2048; i += 256) {
            int row = i >> 4, c16 = (i & 15) * 16;
            cpa16(sbase + row * PITCH_B + c16, Ag + row * 256 + c16);
            cpa16(sbase + SM_B0 + row * PITCH_B + c16, Bg + row * 256 + c16);
        }
        CP_COMMIT();
    }
    if (tid < 128) smin[tid] = 0x7F800000u;

    float best0[4], best1[4];
#pragma unroll
    for (int mf = 0; mf < 4; mf++) { best0[mf] = 1e30f; best1[mf] = 1e30f; }

    uint32_t aAddr = sbase + (uint32_t)((warp_m * 64 + (lane & 15)) * PITCH_B
                                        + ((lane >> 4) & 1) * 16);
    uint32_t bOff  = (uint32_t)((warp_n * 32 + (lane & 7)) * PITCH_B
                                + ((lane >> 3) & 1) * 16);

    for (int c = 0; c < NCH_PER; c++) {
        CP_WAIT0();
        __syncthreads();
        if (c + 1 < NCH_PER) {
            const char* Bg = Tb + (size_t)(g * NCH_PER + c + 1) * 32768;
            uint32_t dstb = sbase + (((c + 1) & 1) ? SM_B1 : SM_B0);
            for (int i = tid; i < 2048; i += 256) {
                int row = i >> 4, c16 = (i & 15) * 16;
                cpa16(dstb + row * PITCH_B + c16, Bg + row * 256 + c16);
            }
            CP_COMMIT();
        }
        uint32_t bAddr = sbase + ((c & 1) ? SM_B1 : SM_B0) + bOff;

        float acc[4][4][4];
#pragma unroll
        for (int mf = 0; mf < 4; mf++)
#pragma unroll
            for (int nf = 0; nf < 4; nf++)
#pragma unroll
                for (int r = 0; r < 4; r++) acc[mf][nf][r] = 0.0f;

#pragma unroll
        for (int ks = 0; ks < 8; ks++) {
            uint32_t a[4][4], b[4][2];
#pragma unroll
            for (int mf = 0; mf < 4; mf++)
                asm volatile(
                    "ldmatrix.sync.aligned.m8n8.x4.shared.b16 {%0,%1,%2,%3}, [%4];"
                    : "=r"(a[mf][0]), "=r"(a[mf][1]), "=r"(a[mf][2]), "=r"(a[mf][3])
                    : "r"(aAddr + mf * 16 * PITCH_B + ks * 32));
#pragma unroll
            for (int nf = 0; nf < 4; nf++)
                asm volatile(
                    "ldmatrix.sync.aligned.m8n8.x2.shared.b16 {%0,%1}, [%2];"
                    : "=r"(b[nf][0]), "=r"(b[nf][1])
                    : "r"(bAddr + nf * 8 * PITCH_B + ks * 32));
#pragma unroll
            for (int mf = 0; mf < 4; mf++)
#pragma unroll
                for (int nf = 0; nf < 4; nf++)
                    asm volatile(
                        "mma.sync.aligned.m16n8k16.row.col.f32.bf16.bf16.f32 "
                        "{%0,%1,%2,%3}, {%4,%5,%6,%7}, {%8,%9}, {%0,%1,%2,%3};"
                        : "+f"(acc[mf][nf][0]), "+f"(acc[mf][nf][1]),
                          "+f"(acc[mf][nf][2]), "+f"(acc[mf][nf][3])
                        : "r"(a[mf][0]), "r"(a[mf][1]), "r"(a[mf][2]), "r"(a[mf][3]),
                          "r"(b[nf][0]), "r"(b[nf][1]));
        }
#pragma unroll
        for (int mf = 0; mf < 4; mf++)
#pragma unroll
            for (int nf = 0; nf < 4; nf++) {
                best0[mf] = fminf(best0[mf], fminf(acc[mf][nf][0], acc[mf][nf][1]));
                best1[mf] = fminf(best1[mf], fminf(acc[mf][nf][2], acc[mf][nf][3]));
            }
    }

#pragma unroll
    for (int mf = 0; mf < 4; mf++) {
        float v0 = best0[mf], v1 = best1[mf];
        v0 = fminf(v0, __shfl_xor_sync(0xffffffffu, v0, 1));
        v0 = fminf(v0, __shfl_xor_sync(0xffffffffu, v0, 2));
        v1 = fminf(v1, __shfl_xor_sync(0xffffffffu, v1, 1));
        v1 = fminf(v1, __shfl_xor_sync(0xffffffffu, v1, 2));
        if ((lane & 3) == 0) {
            int r = warp_m * 64 + mf * 16 + (lane >> 2);
            atomicMin(&smin[r], __float_as_uint(v0));
            atomicMin(&smin[r + 8], __float_as_uint(v1));
        }
    }
    __syncthreads();
    if (tid < 128) {
        int q = qtile * 128 + tid;
        if (q < NQ) atomicMin(&mb[q], smin[tid]);
    }
}

// ---------------- finalize mismatch (both sides) ----------------
__global__ void k_finish(float scale, float* out)
{
    int z = blockIdx.y;
    const unsigned* mb = z ? g_mbB : g_mbA;
    const float* pref = z ? g_prefB : g_prefA;
    __shared__ float sh[256];
    int i = blockIdx.x * 256 + threadIdx.x;
    float c = 0.0f;
    if (i < NQ) {
        float m = __uint_as_float(mb[i]);
        if (m < pref[i] - 1e-4f) c = 1.0f;
    }
    sh[threadIdx.x] = c;
    __syncthreads();
    for (int s = 128; s; s >>= 1) {
        if (threadIdx.x < s) sh[threadIdx.x] += sh[threadIdx.x + s];
        __syncthreads();
    }
    if (threadIdx.x == 0) atomicAdd(out, sh[0] * scale);
}

// ---------------- host ----------------
extern "C" void kernel_launch(void* const* d_in, const int* in_sizes, int n_in,
                              void* d_out, int out_size)
{
    const float* x_w   = (const float*)d_in[0];
    const float* y_w   = (const float*)d_in[1];
    const float* fx_w1 = (const float*)d_in[2];
    const float* fx_b1 = (const float*)d_in[3];
    const float* fx_w2 = (const float*)d_in[4];
    const float* fx_b2 = (const float*)d_in[5];
    const float* gy_w1 = (const float*)d_in[6];
    const float* gy_b1 = (const float*)d_in[7];
    const float* gy_w2 = (const float*)d_in[8];
    const float* gy_b2 = (const float*)d_in[9];
    const int*   imap  = (const int*)d_in[10];
    float* out = (float*)d_out;

    float *xmap, *ymap, *xrt, *yrt;
    cudaGetSymbolAddress((void**)&xmap, g_xmap);
    cudaGetSymbolAddress((void**)&ymap, g_ymap);
    cudaGetSymbolAddress((void**)&xrt,  g_xrt);
    cudaGetSymbolAddress((void**)&yrt,  g_yrt);

    static int smemSet = 0;
    if (!smemSet) {
        cudaFuncSetAttribute(k_nn, cudaFuncAttributeMaxDynamicSharedMemorySize, SMEM_NN);
        cudaFuncSetAttribute(k_mlp2, cudaFuncAttributeMaxDynamicSharedMemorySize,
                             3 * 128 * MP * 4);
        smemSet = 1;
    }

    k_init<<<32, 256>>>(out);
    k_wprep<<<(4 * WSTRIDE + 255) / 256, 256>>>(fx_w1, fx_w2, gy_w1, gy_w2);
    {
        dim3 pg((XPAD_ROWS * 128) / 256, 2);
        k_xpad<<<pg, 256>>>(x_w, y_w, XD, YD);
    }
    int mlpSmem = 3 * 128 * MP * 4;
    dim3 mg(XPAD_ROWS / 128, 2);
    // launch1: z=0 fx(x_w)->xmap ; z=1 gy(y_w)->ymap ; writes padded outputs in place
    k_mlp2<<<mg, 256, mlpSmem>>>(0, 1, fx_b1, fx_b2, gy_b1, gy_b2,
                                 xmap, ymap, XD, YD, YD, XD, 1);
    // launch2: z=0 gy(xmap)->xrt ; z=1 fx(ymap)->yrt
    k_mlp2<<<mg, 256, mlpSmem>>>(1, 0, gy_b1, gy_b2, fx_b1, fx_b2,
                                 xrt, yrt, YD, XD, XD, YD, 0);

    {
        dim3 rg((NROWS + 7) / 8, 2);
        k_rnd<<<rg, 256>>>(xrt, x_w, XD, yrt, y_w, YD, 1.0f / NROWS, out);
        k_tnf<<<rg, 256>>>(y_w, YD, x_w, XD);
    }
    {
        dim3 sg((NQ + 7) / 8, 2);
        k_sup<<<sg, 256>>>(xmap, y_w, YD, ymap, x_w, XD, imap, 1.0f / NQ, out);
    }
    {
        dim3 tg((NTPAD * KP) / 256, 2);
        k_prep_t<<<tg, 256>>>(y_w, YD, x_w, XD);
        dim3 qg((NQPAD * KP + 255) / 256, 2);
        k_prep_q<<<qg, 256>>>(xmap, YD, ymap, XD, imap);
        dim3 fg((NQ + 7) / 8, 2);
        k_pref<<<fg, 256>>>(imap);
    }
    {
        dim3 ng(QTILES, GSPLIT, 2);
        k_nn<<<ng, 256, SMEM_NN>>>();
    }
    {
        dim3 eg((NQ + 255) / 256, 2);
        k_finish<<<eg, 256>>>(1.0f / NQ, out);
    }
}

// round 8
// speedup vs baseline: 7.5985x; 1.0287x over previous
#include <cuda_runtime.h>
#include <cuda_bf16.h>
#include <math.h>
#include <stdint.h>

// ---------------- problem constants ----------------
#define NROWS 25000
#define NQ    8000
#define XD    100
#define YD    120
#define HID   100
#define KP    128
#define NQPAD 8064          // 63*128
#define NTPAD 25088         // 196*128
#define QTILES 63
#define GSPLIT 14
#define NCH_PER 14
#define CSHIFT 8.0f
#define MP    132           // MLP smem/weight pitch (floats)
#define WSTRIDE (128 * MP)  // 16896 words per weight matrix
#define XPAD_ROWS 25088

// ---------------- scratch ----------------
__device__ float g_xmap[NROWS * YD];
__device__ float g_ymap[NROWS * XD];
__device__ float g_xrt [NROWS * XD];
__device__ float g_yrt [NROWS * YD];
__device__ float g_tnY [NROWS];
__device__ float g_tnX [NROWS];
__device__ uint32_t g_Wt[4 * WSTRIDE];
__device__ float g_Xpad[2 * XPAD_ROWS * 128];
__device__ __align__(16) __nv_bfloat16 g_QbA[NQPAD * KP];
__device__ __align__(16) __nv_bfloat16 g_QbB[NQPAD * KP];
__device__ __align__(16) __nv_bfloat16 g_TbA[NTPAD * KP];
__device__ __align__(16) __nv_bfloat16 g_TbB[NTPAD * KP];
__device__ unsigned int g_mbA[NQ];
__device__ unsigned int g_mbB[NQ];
__device__ float g_prefA[NQ];
__device__ float g_prefB[NQ];

// ---------------- helpers ----------------
__device__ __forceinline__ uint32_t smem_u32(const void* p) {
    uint32_t a;
    asm("{ .reg .u64 t; cvta.to.shared.u64 t, %1; cvt.u32.u64 %0, t; }" : "=r"(a) : "l"(p));
    return a;
}
__device__ __forceinline__ void cpa16(uint32_t dst, const void* src) {
    asm volatile("cp.async.cg.shared.global [%0], [%1], 16;" :: "r"(dst), "l"(src));
}
#define CP_COMMIT() asm volatile("cp.async.commit_group;" ::: "memory")
#define CP_WAIT0()  asm volatile("cp.async.wait_group 0;" ::: "memory")

__device__ __forceinline__ uint32_t f2tf32(float v) {
    uint32_t r;
    asm("cvt.rna.tf32.f32 %0, %1;" : "=r"(r) : "f"(v));
    return r;
}

// ---------------- init ----------------
__global__ void k_init(float* out) {
    int i = blockIdx.x * 256 + threadIdx.x;
    if (i == 0) out[0] = 0.0f;
    if (i < NQ) { g_mbA[i] = 0x7F800000u; g_mbB[i] = 0x7F800000u; }
}

// ---------------- weight prep ----------------
__global__ void k_wprep(const float* __restrict__ w0, const float* __restrict__ w1,
                        const float* __restrict__ w2, const float* __restrict__ w3)
{
    int idx = blockIdx.x * 256 + threadIdx.x;
    if (idx >= 4 * WSTRIDE) return;
    int m = idx / WSTRIDE, r = idx - m * WSTRIDE;
    int n = r / MP, k = r - n * MP;
    const float* src; int Kd, Nd;
    if (m == 0)      { src = w0; Kd = XD;  Nd = HID; }
    else if (m == 1) { src = w1; Kd = HID; Nd = YD;  }
    else if (m == 2) { src = w2; Kd = YD;  Nd = HID; }
    else             { src = w3; Kd = HID; Nd = XD;  }
    float v = (n < Nd && k < Kd) ? src[k * Nd + n] : 0.0f;
    g_Wt[idx] = f2tf32(v);
}

// ---------------- input pad ----------------
__global__ void k_xpad(const float* __restrict__ x0, const float* __restrict__ x1,
                       int K0, int K1)
{
    int z = blockIdx.y;
    int idx = blockIdx.x * 256 + threadIdx.x;
    int row = idx >> 7, col = idx & 127;
    const float* src = z ? x1 : x0;
    int Kin = z ? K1 : K0;
    float v = (row < NROWS && col < Kin) ? src[(size_t)row * Kin + col] : 0.0f;
    g_Xpad[(size_t)z * (XPAD_ROWS * 128) + idx] = __uint_as_float(f2tf32(v));
}

// ---------------- fused 2-layer MLP, 512 threads (16 warps, 4m x 4n) --------
__global__ __launch_bounds__(512, 1)
void k_mlp2(int wsel0, int wsel1,
            const float* __restrict__ b1_0, const float* __restrict__ b2_0,
            const float* __restrict__ b1_1, const float* __restrict__ b2_1,
            float* __restrict__ Y0, float* __restrict__ Y1,
            int Kin0, int Nout0, int Kin1, int Nout1, int writePad)
{
    extern __shared__ __align__(16) uint32_t sm[];
    uint32_t* Xs  = sm;
    uint32_t* W1t = Xs + 128 * MP;
    uint32_t* W2t = W1t + 128 * MP;
    int tid = threadIdx.x, lane = tid & 31, wid = tid >> 5;
    int warp_m = wid >> 2, warp_n = wid & 3;        // 4 x 4
    int z = blockIdx.y;
    int m0 = blockIdx.x * 128;

    int wsel = z ? wsel1 : wsel0;
    int Kin  = z ? Kin1 : Kin0;
    int Nout = z ? Nout1 : Nout0;
    const float* B1 = z ? b1_1 : b1_0;
    const float* B2 = z ? b2_1 : b2_0;
    float* Y = z ? Y1 : Y0;
    float* Xpad = g_Xpad + (size_t)z * (XPAD_ROWS * 128);

    // prologue: pure cp.async
    {
        uint32_t sX = smem_u32(Xs);
        const float* xsrc = Xpad + (size_t)m0 * 128;
        for (int i = tid; i < 4096; i += 512) {
            int r = i >> 5, c = i & 31;
            cpa16(sX + r * (MP * 4) + c * 16, xsrc + r * 128 + c * 4);
        }
        uint32_t sW = smem_u32(W1t);
        const char* wsrc = (const char*)(g_Wt + wsel * 2 * WSTRIDE);
        for (int i = tid; i < 8448; i += 512)
            cpa16(sW + i * 16, wsrc + i * 16);
        CP_COMMIT();
        CP_WAIT0();
    }
    __syncthreads();

    int r0 = lane >> 2, c0 = lane & 3;
    float acc[2][4][4];
    // stage1: cols >= 104 dead (HID=100)
    int nf1max = (warp_n < 3) ? 4 : 1;
    int nf2max = (warp_n < 3) ? 4 : ((Nout > 104) ? 3 : 1);

    // ---------------- stage 1 ----------------
#pragma unroll
    for (int mf = 0; mf < 2; mf++)
#pragma unroll
        for (int nf = 0; nf < 4; nf++)
#pragma unroll
            for (int r = 0; r < 4; r++) acc[mf][nf][r] = 0.0f;

    int ks1 = (Kin + 7) >> 3;
    for (int ks = 0; ks < ks1; ks++) {
        int kb = ks * 8;
        uint32_t a[2][4], b[4][2];
#pragma unroll
        for (int mf = 0; mf < 2; mf++) {
            int row = warp_m * 32 + mf * 16 + r0;
            const uint32_t* p = &Xs[row * MP + kb + c0];
            a[mf][0] = p[0]; a[mf][1] = p[8 * MP]; a[mf][2] = p[4]; a[mf][3] = p[8 * MP + 4];
        }
#pragma unroll
        for (int nf = 0; nf < 4; nf++) {
            if (nf < nf1max) {
                int col = warp_n * 32 + nf * 8 + r0;
                const uint32_t* p = &W1t[col * MP + kb + c0];
                b[nf][0] = p[0]; b[nf][1] = p[4];
            }
        }
#pragma unroll
        for (int mf = 0; mf < 2; mf++)
#pragma unroll
            for (int nf = 0; nf < 4; nf++)
                if (nf < nf1max)
                    asm volatile(
                        "mma.sync.aligned.m16n8k8.row.col.f32.tf32.tf32.f32 "
                        "{%0,%1,%2,%3}, {%4,%5,%6,%7}, {%8,%9}, {%0,%1,%2,%3};"
                        : "+f"(acc[mf][nf][0]), "+f"(acc[mf][nf][1]),
                          "+f"(acc[mf][nf][2]), "+f"(acc[mf][nf][3])
                        : "r"(a[mf][0]), "r"(a[mf][1]), "r"(a[mf][2]), "r"(a[mf][3]),
                          "r"(b[nf][0]), "r"(b[nf][1]));
    }
    __syncthreads();

    // H = relu(acc + b1) -> Xs (cols >= HID zeroed)
#pragma unroll
    for (int mf = 0; mf < 2; mf++)
#pragma unroll
        for (int nf = 0; nf < 4; nf++) {
            int row = warp_m * 32 + mf * 16 + r0;
            int col = warp_n * 32 + nf * 8 + c0 * 2;
            float bi0 = (col < HID) ? B1[col] : 0.0f;
            float bi1 = (col + 1 < HID) ? B1[col + 1] : 0.0f;
            float v0 = (col < HID) ? fmaxf(acc[mf][nf][0] + bi0, 0.0f) : 0.0f;
            float v1 = (col + 1 < HID) ? fmaxf(acc[mf][nf][1] + bi1, 0.0f) : 0.0f;
            float v2 = (col < HID) ? fmaxf(acc[mf][nf][2] + bi0, 0.0f) : 0.0f;
            float v3 = (col + 1 < HID) ? fmaxf(acc[mf][nf][3] + bi1, 0.0f) : 0.0f;
            Xs[row * MP + col]           = f2tf32(v0);
            Xs[row * MP + col + 1]       = f2tf32(v1);
            Xs[(row + 8) * MP + col]     = f2tf32(v2);
            Xs[(row + 8) * MP + col + 1] = f2tf32(v3);
        }
    __syncthreads();

    // ---------------- stage 2 ----------------
#pragma unroll
    for (int mf = 0; mf < 2; mf++)
#pragma unroll
        for (int nf = 0; nf < 4; nf++)
#pragma unroll
            for (int r = 0; r < 4; r++) acc[mf][nf][r] = 0.0f;

    const int ks2 = (HID + 7) >> 3;
    for (int ks = 0; ks < ks2; ks++) {
        int kb = ks * 8;
        uint32_t a[2][4], b[4][2];
#pragma unroll
        for (int mf = 0; mf < 2; mf++) {
            int row = warp_m * 32 + mf * 16 + r0;
            const uint32_t* p = &Xs[row * MP + kb + c0];
            a[mf][0] = p[0]; a[mf][1] = p[8 * MP]; a[mf][2] = p[4]; a[mf][3] = p[8 * MP + 4];
        }
#pragma unroll
        for (int nf = 0; nf < 4; nf++) {
            if (nf < nf2max) {
                int col = warp_n * 32 + nf * 8 + r0;
                const uint32_t* p = &W2t[col * MP + kb + c0];
                b[nf][0] = p[0]; b[nf][1] = p[4];
            }
        }
#pragma unroll
        for (int mf = 0; mf < 2; mf++)
#pragma unroll
            for (int nf = 0; nf < 4; nf++)
                if (nf < nf2max)
                    asm volatile(
                        "mma.sync.aligned.m16n8k8.row.col.f32.tf32.tf32.f32 "
                        "{%0,%1,%2,%3}, {%4,%5,%6,%7}, {%8,%9}, {%0,%1,%2,%3};"
                        : "+f"(acc[mf][nf][0]), "+f"(acc[mf][nf][1]),
                          "+f"(acc[mf][nf][2]), "+f"(acc[mf][nf][3])
                        : "r"(a[mf][0]), "r"(a[mf][1]), "r"(a[mf][2]), "r"(a[mf][3]),
                          "r"(b[nf][0]), "r"(b[nf][1]));
    }

    // epilogue
#pragma unroll
    for (int mf = 0; mf < 2; mf++)
#pragma unroll
        for (int nf = 0; nf < 4; nf++) {
            int row = warp_m * 32 + mf * 16 + r0;
            int col = warp_n * 32 + nf * 8 + c0 * 2;
            float bi0 = (col < Nout) ? B2[col] : 0.0f;
            float bi1 = (col + 1 < Nout) ? B2[col + 1] : 0.0f;
            float v0 = (col < Nout) ? acc[mf][nf][0] + bi0 : 0.0f;
            float v1 = (col + 1 < Nout) ? acc[mf][nf][1] + bi1 : 0.0f;
            float v2 = (col < Nout) ? acc[mf][nf][2] + bi0 : 0.0f;
            float v3 = (col + 1 < Nout) ? acc[mf][nf][3] + bi1 : 0.0f;
            if (m0 + row < NROWS) {
                if (col < Nout)
                    *(float2*)&Y[(size_t)(m0 + row) * Nout + col] = make_float2(v0, v1);
                if (writePad)
                    *(float2*)&Xpad[(size_t)(m0 + row) * 128 + col] =
                        make_float2(__uint_as_float(f2tf32(v0)), __uint_as_float(f2tf32(v1)));
            }
            if (m0 + row + 8 < NROWS) {
                if (col < Nout)
                    *(float2*)&Y[(size_t)(m0 + row + 8) * Nout + col] = make_float2(v2, v3);
                if (writePad)
                    *(float2*)&Xpad[(size_t)(m0 + row + 8) * 128 + col] =
                        make_float2(__uint_as_float(f2tf32(v2)), __uint_as_float(f2tf32(v3)));
            }
        }
}

// ---------------- fused reductions ----------------
__global__ void k_rnd(const float* __restrict__ A0, const float* __restrict__ B0, int K0,
                      const float* __restrict__ A1, const float* __restrict__ B1, int K1,
                      float scale, float* out)
{
    int z = blockIdx.y;
    const float* A = z ? A1 : A0; const float* B = z ? B1 : B0;
    int Kc = z ? K1 : K0;
    int w = threadIdx.x >> 5, lane = threadIdx.x & 31;
    int row = blockIdx.x * 8 + w;
    float r = 0.0f;
    if (row < NROWS) {
        const float* a = A + (size_t)row * Kc;
        const float* b = B + (size_t)row * Kc;
        float s = 0.0f;
        for (int j = lane; j < Kc; j += 32) { float d = a[j] - b[j]; s = fmaf(d, d, s); }
#pragma unroll
        for (int o = 16; o; o >>= 1) s += __shfl_xor_sync(0xffffffffu, s, o);
        r = sqrtf(s);
    }
    __shared__ float sh[8];
    if (lane == 0) sh[w] = r;
    __syncthreads();
    if (threadIdx.x == 0) {
        float t = 0.0f;
#pragma unroll
        for (int i = 0; i < 8; i++) t += sh[i];
        atomicAdd(out, t * scale);
    }
}

__global__ void k_sup(const float* __restrict__ A0, const float* __restrict__ B0, int K0,
                      const float* __restrict__ A1, const float* __restrict__ B1, int K1,
                      const int* __restrict__ imap, float scale, float* out)
{
    int z = blockIdx.y;
    const float* A = z ? A1 : A0; const float* B = z ? B1 : B0;
    int Kc = z ? K1 : K0; int aSel = z;
    int w = threadIdx.x >> 5, lane = threadIdx.x & 31;
    int i = blockIdx.x * 8 + w;
    float r = 0.0f;
    if (i < NQ) {
        const float* a = A + (size_t)imap[2 * i + aSel] * Kc;
        const float* b = B + (size_t)imap[2 * i + 1 - aSel] * Kc;
        float s = 0.0f;
        for (int j = lane; j < Kc; j += 32) { float d = a[j] - b[j]; s = fmaf(d, d, s); }
#pragma unroll
        for (int o = 16; o; o >>= 1) s += __shfl_xor_sync(0xffffffffu, s, o);
        r = sqrtf(s);
    }
    __shared__ float sh[8];
    if (lane == 0) sh[w] = r;
    __syncthreads();
    if (threadIdx.x == 0) {
        float t = 0.0f;
#pragma unroll
        for (int k = 0; k < 8; k++) t += sh[k];
        atomicAdd(out, t * scale);
    }
}

__global__ void k_tnf(const float* __restrict__ T0, int K0, const float* __restrict__ T1, int K1)
{
    int z = blockIdx.y;
    const float* T = z ? T1 : T0; int Kc = z ? K1 : K0;
    float* tn = z ? g_tnX : g_tnY;
    int w = threadIdx.x >> 5, lane = threadIdx.x & 31;
    int row = blockIdx.x * 8 + w;
    if (row >= NROWS) return;
    const float* a = T + (size_t)row * Kc;
    float s = 0.0f;
    for (int j = lane; j < Kc; j += 32) s = fmaf(a[j], a[j], s);
#pragma unroll
    for (int o = 16; o; o >>= 1) s += __shfl_xor_sync(0xffffffffu, s, o);
    if (lane == 0) tn[row] = s;
}

// ---------------- bf16 NN preps ----------------
__global__ void k_prep_t(const float* __restrict__ T0, int K0,
                         const float* __restrict__ T1, int K1)
{
    int z = blockIdx.y;
    const float* T = z ? T1 : T0; int K = z ? K1 : K0;
    const float* tn = z ? g_tnX : g_tnY;
    __nv_bfloat16* Tb = z ? g_TbB : g_TbA;
    int idx = blockIdx.x * 256 + threadIdx.x;
    if (idx >= NTPAD * KP) return;
    int row = idx >> 7, col = idx & 127;
    float v = 0.0f;
    if (row < NROWS) {
        if (col < K) v = T[(size_t)row * K + col];
        else if (col == K) v = CSHIFT + tn[row];
        else if (col == K + 1) {
            float s = CSHIFT + tn[row];
            v = s - __bfloat162float(__float2bfloat16(s));
        }
    } else if (col == K) v = 1.0e6f;
    Tb[idx] = __float2bfloat16(v);
}

__global__ void k_prep_q(const float* __restrict__ m0, int K0,
                         const float* __restrict__ m1, int K1,
                         const int* __restrict__ imap)
{
    int z = blockIdx.y;
    const float* mapped = z ? m1 : m0; int K = z ? K1 : K0; int sel = z;
    __nv_bfloat16* Qb = z ? g_QbB : g_QbA;
    int idx = blockIdx.x * 256 + threadIdx.x;
    if (idx >= NQPAD * KP) return;
    int row = idx >> 7, col = idx & 127;
    float v = 0.0f;
    if (row < NQ) {
        if (col < K) v = -2.0f * mapped[(size_t)imap[2 * row + sel] * K + col];
        else if (col <= K + 1) v = 1.0f;
    }
    Qb[idx] = __float2bfloat16(v);
}

__global__ void k_pref(const int* __restrict__ imap)
{
    int z = blockIdx.y;
    const __nv_bfloat16* Qb = z ? g_QbB : g_QbA;
    const __nv_bfloat16* Tb = z ? g_TbB : g_TbA;
    float* pref = z ? g_prefB : g_prefA;
    int w = threadIdx.x >> 5, lane = threadIdx.x & 31;
    int q = blockIdx.x * 8 + w;
    if (q >= NQ) return;
    int t = imap[2 * q + z];
    const __nv_bfloat16* qr = Qb + (size_t)q * KP;
    const __nv_bfloat16* tr = Tb + (size_t)t * KP;
    float s = 0.0f;
#pragma unroll
    for (int k = lane; k < KP; k += 32)
        s = fmaf(__bfloat162float(qr[k]), __bfloat162float(tr[k]), s);
#pragma unroll
    for (int o = 16; o; o >>= 1) s += __shfl_xor_sync(0xffffffffu, s, o);
    if (lane == 0) pref[q] = s;
}

// ---------------- mma.sync 1-NN proxy-min (templated on K-steps) -------------
#define PITCH_B 272
#define SM_B0   (128 * PITCH_B)
#define SM_B1   (SM_B0 + 128 * PITCH_B)
#define SM_MIN  (SM_B1 + 128 * PITCH_B)
#define SMEM_NN (SM_MIN + 512)

template <int NKS>
__device__ __forceinline__ void nn_side(const char* __restrict__ Qb,
                                        const char* __restrict__ Tb,
                                        unsigned* __restrict__ mb,
                                        char* dsm)
{
    constexpr int NC16 = NKS * 2;   // 16B col-chunks per row to copy
    uint32_t sbase = smem_u32(dsm);
    unsigned* smin = (unsigned*)(dsm + SM_MIN);
    int tid = threadIdx.x, lane = tid & 31, wid = tid >> 5;
    int warp_m = wid >> 2, warp_n = wid & 3;
    int qtile = blockIdx.x, g = blockIdx.y;

    {
        const char* Ag = Qb + (size_t)qtile * 32768;
        const char* Bg = Tb + (size_t)(g * NCH_PER) * 32768;
        for (int i = tid; i < 2048; i += 256) {
            int row = i >> 4, c16 = i & 15;
            if (c16 < NC16) {
                cpa16(sbase + row * PITCH_B + c16 * 16, Ag + row * 256 + c16 * 16);
                cpa16(sbase + SM_B0 + row * PITCH_B + c16 * 16, Bg + row * 256 + c16 * 16);
            }
        }
        CP_COMMIT();
    }
    if (tid < 128) smin[tid] = 0x7F800000u;

    float best0[4], best1[4];
#pragma unroll
    for (int mf = 0; mf < 4; mf++) { best0[mf] = 1e30f; best1[mf] = 1e30f; }

    uint32_t aAddr = sbase + (uint32_t)((warp_m * 64 + (lane & 15)) * PITCH_B
                                        + ((lane >> 4) & 1) * 16);
    uint32_t bOff  = (uint32_t)((warp_n * 32 + (lane & 7)) * PITCH_B
                                + ((lane >> 3) & 1) * 16);

    for (int c = 0; c < NCH_PER; c++) {
        CP_WAIT0();
        __syncthreads();
        if (c + 1 < NCH_PER) {
            const char* Bg = Tb + (size_t)(g * NCH_PER + c + 1) * 32768;
            uint32_t dstb = sbase + (((c + 1) & 1) ? SM_B1 : SM_B0);
            for (int i = tid; i < 2048; i += 256) {
                int row = i >> 4, c16 = i & 15;
                if (c16 < NC16)
                    cpa16(dstb + row * PITCH_B + c16 * 16, Bg + row * 256 + c16 * 16);
            }
            CP_COMMIT();
        }
        uint32_t bAddr = sbase + ((c & 1) ? SM_B1 : SM_B0) + bOff;

        float acc[4][4][4];
#pragma unroll
        for (int mf = 0; mf < 4; mf++)
#pragma unroll
            for (int nf = 0; nf < 4; nf++)
#pragma unroll
                for (int r = 0; r < 4; r++) acc[mf][nf][r] = 0.0f;

#pragma unroll
        for (int ks = 0; ks < NKS; ks++) {
            uint32_t a[4][4], b[4][2];
#pragma unroll
            for (int mf = 0; mf < 4; mf++)
                asm volatile(
                    "ldmatrix.sync.aligned.m8n8.x4.shared.b16 {%0,%1,%2,%3}, [%4];"
                    : "=r"(a[mf][0]), "=r"(a[mf][1]), "=r"(a[mf][2]), "=r"(a[mf][3])
                    : "r"(aAddr + mf * 16 * PITCH_B + ks * 32));
#pragma unroll
            for (int nf = 0; nf < 4; nf++)
                asm volatile(
                    "ldmatrix.sync.aligned.m8n8.x2.shared.b16 {%0,%1}, [%2];"
                    : "=r"(b[nf][0]), "=r"(b[nf][1])
                    : "r"(bAddr + nf * 8 * PITCH_B + ks * 32));
#pragma unroll
            for (int mf = 0; mf < 4; mf++)
#pragma unroll
                for (int nf = 0; nf < 4; nf++)
                    asm volatile(
                        "mma.sync.aligned.m16n8k16.row.col.f32.bf16.bf16.f32 "
                        "{%0,%1,%2,%3}, {%4,%5,%6,%7}, {%8,%9}, {%0,%1,%2,%3};"
                        : "+f"(acc[mf][nf][0]), "+f"(acc[mf][nf][1]),
                          "+f"(acc[mf][nf][2]), "+f"(acc[mf][nf][3])
                        : "r"(a[mf][0]), "r"(a[mf][1]), "r"(a[mf][2]), "r"(a[mf][3]),
                          "r"(b[nf][0]), "r"(b[nf][1]));
        }
#pragma unroll
        for (int mf = 0; mf < 4; mf++)
#pragma unroll
            for (int nf = 0; nf < 4; nf++) {
                best0[mf] = fminf(best0[mf], fminf(acc[mf][nf][0], acc[mf][nf][1]));
                best1[mf] = fminf(best1[mf], fminf(acc[mf][nf][2], acc[mf][nf][3]));
            }
    }

#pragma unroll
    for (int mf = 0; mf < 4; mf++) {
        float v0 = best0[mf], v1 = best1[mf];
        v0 = fminf(v0, __shfl_xor_sync(0xffffffffu, v0, 1));
        v0 = fminf(v0, __shfl_xor_sync(0xffffffffu, v0, 2));
        v1 = fminf(v1, __shfl_xor_sync(0xffffffffu, v1, 1));
        v1 = fminf(v1, __shfl_xor_sync(0xffffffffu, v1, 2));
        if ((lane & 3) == 0) {
            int r = warp_m * 64 + mf * 16 + (lane >> 2);
            atomicMin(&smin[r], __float_as_uint(v0));
            atomicMin(&smin[r + 8], __float_as_uint(v1));
        }
    }
    __syncthreads();
    if (tid < 128) {
        int q = qtile * 128 + tid;
        if (q < NQ) atomicMin(&mb[q], smin[tid]);
    }
}

__global__ __launch_bounds__(256, 2)
void k_nn()
{
    extern __shared__ __align__(16) char dsm[];
    if (blockIdx.z == 0)
        nn_side<8>((const char*)g_QbA, (const char*)g_TbA, g_mbA, dsm);
    else
        nn_side<7>((const char*)g_QbB, (const char*)g_TbB, g_mbB, dsm);
}

// ---------------- finalize mismatch ----------------
__global__ void k_finish(float scale, float* out)
{
    int z = blockIdx.y;
    const unsigned* mb = z ? g_mbB : g_mbA;
    const float* pref = z ? g_prefB : g_prefA;
    __shared__ float sh[256];
    int i = blockIdx.x * 256 + threadIdx.x;
    float c = 0.0f;
    if (i < NQ) {
        float m = __uint_as_float(mb[i]);
        if (m < pref[i] - 1e-4f) c = 1.0f;
    }
    sh[threadIdx.x] = c;
    __syncthreads();
    for (int s = 128; s; s >>= 1) {
        if (threadIdx.x < s) sh[threadIdx.x] += sh[threadIdx.x + s];
        __syncthreads();
    }
    if (threadIdx.x == 0) atomicAdd(out, sh[0] * scale);
}

// ---------------- host ----------------
extern "C" void kernel_launch(void* const* d_in, const int* in_sizes, int n_in,
                              void* d_out, int out_size)
{
    const float* x_w   = (const float*)d_in[0];
    const float* y_w   = (const float*)d_in[1];
    const float* fx_w1 = (const float*)d_in[2];
    const float* fx_b1 = (const float*)d_in[3];
    const float* fx_w2 = (const float*)d_in[4];
    const float* fx_b2 = (const float*)d_in[5];
    const float* gy_w1 = (const float*)d_in[6];
    const float* gy_b1 = (const float*)d_in[7];
    const float* gy_w2 = (const float*)d_in[8];
    const float* gy_b2 = (const float*)d_in[9];
    const int*   imap  = (const int*)d_in[10];
    float* out = (float*)d_out;

    float *xmap, *ymap, *xrt, *yrt;
    cudaGetSymbolAddress((void**)&xmap, g_xmap);
    cudaGetSymbolAddress((void**)&ymap, g_ymap);
    cudaGetSymbolAddress((void**)&xrt,  g_xrt);
    cudaGetSymbolAddress((void**)&yrt,  g_yrt);

    static int smemSet = 0;
    if (!smemSet) {
        cudaFuncSetAttribute(k_nn, cudaFuncAttributeMaxDynamicSharedMemorySize, SMEM_NN);
        cudaFuncSetAttribute(k_mlp2, cudaFuncAttributeMaxDynamicSharedMemorySize,
                             3 * 128 * MP * 4);
        smemSet = 1;
    }

    k_init<<<32, 256>>>(out);
    k_wprep<<<(4 * WSTRIDE + 255) / 256, 256>>>(fx_w1, fx_w2, gy_w1, gy_w2);
    {
        dim3 pg((XPAD_ROWS * 128) / 256, 2);
        k_xpad<<<pg, 256>>>(x_w, y_w, XD, YD);
    }
    int mlpSmem = 3 * 128 * MP * 4;
    dim3 mg(XPAD_ROWS / 128, 2);
    k_mlp2<<<mg, 512, mlpSmem>>>(0, 1, fx_b1, fx_b2, gy_b1, gy_b2,
                                 xmap, ymap, XD, YD, YD, XD, 1);
    k_mlp2<<<mg, 512, mlpSmem>>>(1, 0, gy_b1, gy_b2, fx_b1, fx_b2,
                                 xrt, yrt, YD, XD, XD, YD, 0);

    {
        dim3 rg((NROWS + 7) / 8, 2);
        k_rnd<<<rg, 256>>>(xrt, x_w, XD, yrt, y_w, YD, 1.0f / NROWS, out);
        k_tnf<<<rg, 256>>>(y_w, YD, x_w, XD);
    }
    {
        dim3 sg((NQ + 7) / 8, 2);
        k_sup<<<sg, 256>>>(xmap, y_w, YD, ymap, x_w, XD, imap, 1.0f / NQ, out);
    }
    {
        dim3 tg((NTPAD * KP) / 256, 2);
        k_prep_t<<<tg, 256>>>(y_w, YD, x_w, XD);
        dim3 qg((NQPAD * KP + 255) / 256, 2);
        k_prep_q<<<qg, 256>>>(xmap, YD, ymap, XD, imap);
        dim3 fg((NQ + 7) / 8, 2);
        k_pref<<<fg, 256>>>(imap);
    }
    {
        dim3 ng(QTILES, GSPLIT, 2);
        k_nn<<<ng, 256, SMEM_NN>>>();
    }
    {
        dim3 eg((NQ + 255) / 256, 2);
        k_finish<<<eg, 256>>>(1.0f / NQ, out);
    }
}